// round 12
// baseline (speedup 1.0000x reference)
#include <cuda_runtime.h>
#include <cuda_bf16.h>
#include <cuda_fp16.h>
#include <math.h>
#include <stdint.h>

#define TOKENS 16384
#define DMODEL 768
#define NHEAD  12
#define HDIM   64
#define DMLP   3072
#define SEQ    1024
#define BATCH  16

// ---------------- scratch (device globals; no cudaMalloc allowed) ----------------
__device__ __half g_lnx [TOKENS * DMODEL];   // LN1 out f16 (qkv input)
__device__ __half g_lnh [TOKENS * DMODEL];   // LN2 out f16
__device__ __half g_qf  [TOKENS * DMODEL];   // q f16, pre-scaled by 0.125 [tok][h*64+d]
__device__ __half g_kf  [TOKENS * DMODEL];   // k f16
__device__ __half g_vt  [TOKENS * DMODEL];   // V^T f16: [(b*12+h)*64+d][1024]
__device__ float  g_x1  [TOKENS * DMODEL];   // x + attn
__device__ __half g_acth[TOKENS * DMLP];     // GELU out f16
__device__ __half g_w1h [DMLP * DMODEL];     // W1 f16
__device__ __half g_w2h [DMODEL * DMLP];     // W2 f16
__device__ __half g_wqkv[3 * NHEAD * HDIM * HDIM];  // Wq|Wk|Wv f16

// ---------------- PTX helpers (portable sm_80-class only) ----------------
__device__ __forceinline__ void cp16(uint32_t s, const void* g) {
    asm volatile("cp.async.cg.shared.global [%0], [%1], 16;" :: "r"(s), "l"(g));
}
__device__ __forceinline__ void cp_commit() { asm volatile("cp.async.commit_group;" ::: "memory"); }
__device__ __forceinline__ void cp_wait1()  { asm volatile("cp.async.wait_group 1;" ::: "memory"); }
__device__ __forceinline__ void cp_wait0()  { asm volatile("cp.async.wait_group 0;" ::: "memory"); }

__device__ __forceinline__ void ldsm4(uint32_t* r, uint32_t addr) {
    asm volatile("ldmatrix.sync.aligned.m8n8.x4.shared.b16 {%0,%1,%2,%3}, [%4];"
                 : "=r"(r[0]), "=r"(r[1]), "=r"(r[2]), "=r"(r[3]) : "r"(addr));
}
__device__ __forceinline__ void mma_f16(float* d, const uint32_t* a, const uint32_t* b) {
    asm("mma.sync.aligned.m16n8k16.row.col.f32.f16.f16.f32 "
        "{%0,%1,%2,%3}, {%4,%5,%6,%7}, {%8,%9}, {%0,%1,%2,%3};"
        : "+f"(d[0]), "+f"(d[1]), "+f"(d[2]), "+f"(d[3])
        : "r"(a[0]), "r"(a[1]), "r"(a[2]), "r"(a[3]), "r"(b[0]), "r"(b[1]));
}
__device__ __forceinline__ uint32_t f16x2(float hi, float lo) {
    uint32_t u;
    asm("cvt.rn.f16x2.f32 %0, %1, %2;" : "=r"(u) : "f"(hi), "f"(lo));
    return u;
}

// ---------------- LayerNorm (f16 out) ----------------
__global__ void ln_f16_kernel(const float* __restrict__ x, const float* __restrict__ g,
                              const float* __restrict__ b, __half* __restrict__ oh)
{
    int tok = blockIdx.x;
    int t = threadIdx.x;
    const float* xr = x + (size_t)tok * DMODEL;
    float v0 = xr[t], v1 = xr[t + 256], v2 = xr[t + 512];
    float s = v0 + v1 + v2;
    __shared__ float red[8];
#pragma unroll
    for (int o = 16; o > 0; o >>= 1) s += __shfl_xor_sync(0xffffffffu, s, o);
    if ((t & 31) == 0) red[t >> 5] = s;
    __syncthreads();
    float tot = 0.f;
#pragma unroll
    for (int i = 0; i < 8; i++) tot += red[i];
    float mu = tot * (1.0f / DMODEL);
    float d0 = v0 - mu, d1 = v1 - mu, d2 = v2 - mu;
    float sq = d0 * d0 + d1 * d1 + d2 * d2;
#pragma unroll
    for (int o = 16; o > 0; o >>= 1) sq += __shfl_xor_sync(0xffffffffu, sq, o);
    __syncthreads();
    if ((t & 31) == 0) red[t >> 5] = sq;
    __syncthreads();
    float vs = 0.f;
#pragma unroll
    for (int i = 0; i < 8; i++) vs += red[i];
    float rs = rsqrtf(vs * (1.0f / DMODEL) + 1e-5f);
    size_t base = (size_t)tok * DMODEL;
    oh[base + t]       = __float2half(d0 * rs * g[t]       + b[t]);
    oh[base + t + 256] = __float2half(d1 * rs * g[t + 256] + b[t + 256]);
    oh[base + t + 512] = __float2half(d2 * rs * g[t + 512] + b[t + 512]);
}

// ---------------- weight conversions ----------------
__global__ void convert_w_kernel(const float* __restrict__ W, __half* __restrict__ wh, int n)
{
    int i = blockIdx.x * 256 + threadIdx.x;
    if (i < n) wh[i] = __float2half(W[i]);
}
__global__ void convert_wqkv_kernel(const float* __restrict__ Wq, const float* __restrict__ Wk,
                                    const float* __restrict__ Wv, __half* __restrict__ o)
{
    int i = blockIdx.x * 256 + threadIdx.x;
    const int n = NHEAD * HDIM * HDIM;
    if (i < n) {
        o[i]         = __float2half(Wq[i]);
        o[n + i]     = __float2half(Wk[i]);
        o[2 * n + i] = __float2half(Wv[i]);
    }
}

// ---------------- shared swizzle: 128B rows, 8 x 16B chunks ----------------
__device__ __forceinline__ uint32_t sw(uint32_t b, int row, int ch) {
    return b + (uint32_t)(row * 128) + (uint32_t)((ch ^ (row & 7)) << 4);
}

// ---------------- HMMA QKV: per-CTA 128 tokens x one head (unchanged R11) ----------------
#define QX_OFF  0
#define QW_OFF  16384
#define QV_OFF  (16384 + 3 * 8192)
#define QKV_SMEM (QV_OFF + 64 * 272)

__global__ void __launch_bounds__(256, 1) qkv_mma_kernel(
    const __half* __restrict__ lnx, const __half* __restrict__ wqkv,
    const float* __restrict__ bq, const float* __restrict__ bk, const float* __restrict__ bv,
    __half* __restrict__ qf, __half* __restrict__ kf, __half* __restrict__ vt)
{
    extern __shared__ char dsm[];
    uint32_t sb = (uint32_t)__cvta_generic_to_shared(dsm);
    const int hh = blockIdx.y;
    const int t0 = blockIdx.x * 128;
    const int t = threadIdx.x, lane = t & 31, w = t >> 5;
    const int ho = hh * HDIM;
    const int bh = (t0 >> 10) * 12 + hh;

#pragma unroll
    for (int i = 0; i < 4; i++) {
        int idx = t + 256 * i;
        int r = idx >> 3, c = idx & 7;
        cp16(sw(sb + QX_OFF, r, c), lnx + (size_t)(t0 + r) * DMODEL + ho + c * 8);
    }
#pragma unroll
    for (int m = 0; m < 3; m++)
#pragma unroll
        for (int i = 0; i < 2; i++) {
            int idx = t + 256 * i;
            int r = idx >> 3, c = idx & 7;
            cp16(sw(sb + QW_OFF + m * 8192, r, c),
                 wqkv + (size_t)(m * NHEAD + hh) * 4096 + r * 64 + c * 8);
        }
    cp_commit();
    cp_wait0();
    __syncthreads();

    uint32_t af[4][4];
#pragma unroll
    for (int ks = 0; ks < 4; ks++) {
        int r = w * 16 + (lane & 15);
        int c = ks * 2 + (lane >> 4);
        ldsm4(af[ks], sw(sb + QX_OFF, r, c));
    }

    const float* biases[3] = { bq + ho, bk + ho, bv + ho };

#pragma unroll
    for (int m = 0; m < 3; m++) {
        float acc[8][4] = {};
        uint32_t wb0 = sb + QW_OFF + m * 8192;
#pragma unroll
        for (int kp = 0; kp < 2; kp++) {
            uint32_t bf[8][4];
#pragma unroll
            for (int j = 0; j < 8; j++) {
                int r = j * 8 + (lane & 7);
                int c = kp * 4 + ((lane >> 3) & 3);
                ldsm4(bf[j], sw(wb0, r, c));
            }
#pragma unroll
            for (int s = 0; s < 2; s++)
#pragma unroll
                for (int j = 0; j < 8; j++)
                    mma_f16(acc[j], af[kp * 2 + s], &bf[j][s * 2]);
        }
        const float* bias = biases[m];
        int r0 = w * 16 + (lane >> 2);
        int cb = 2 * (lane & 3);
        if (m < 2) {
            __half* dst = (m == 0) ? qf : kf;
            float scale = (m == 0) ? 0.125f : 1.0f;
#pragma unroll
            for (int j = 0; j < 8; j++)
#pragma unroll
                for (int h2 = 0; h2 < 2; h2++) {
                    int col = cb + j * 8;
                    int row = t0 + r0 + h2 * 8;
                    float v0 = (acc[j][h2 * 2 + 0] + bias[col])     * scale;
                    float v1 = (acc[j][h2 * 2 + 1] + bias[col + 1]) * scale;
                    *(uint32_t*)(dst + (size_t)row * DMODEL + ho + col) = f16x2(v1, v0);
                }
        } else {
#pragma unroll
            for (int j = 0; j < 8; j++)
#pragma unroll
                for (int h2 = 0; h2 < 2; h2++) {
                    int col = cb + j * 8;
                    int rl  = r0 + h2 * 8;
                    float v0 = acc[j][h2 * 2 + 0] + bias[col];
                    float v1 = acc[j][h2 * 2 + 1] + bias[col + 1];
                    *(__half*)(dsm + QV_OFF + col * 272 + rl * 2)       = __float2half(v0);
                    *(__half*)(dsm + QV_OFF + (col + 1) * 272 + rl * 2) = __float2half(v1);
                }
        }
    }
    __syncthreads();
    int pos0 = t0 & 1023;
#pragma unroll
    for (int i = 0; i < 4; i++) {
        int idx = t + 256 * i;
        int o = idx >> 4, q16 = idx & 15;
        uint4 val = *(const uint4*)(dsm + QV_OFF + o * 272 + q16 * 16);
        *(uint4*)(vt + ((size_t)(bh * 64 + o)) * 1024 + pos0 + q16 * 8) = val;
    }
}

// ---------------- HMMA flash attention: 512 threads, 256 queries/CTA, 3-stage ----------------
#define AT_BUF 16384   // per-stage: K 8KB + Vt 8KB

__global__ void __launch_bounds__(512, 1) attn_mma_kernel(
    const __half* __restrict__ qf, const __half* __restrict__ kf,
    const __half* __restrict__ vt,
    const float* __restrict__ x, float* __restrict__ out)
{
    extern __shared__ char dsm[];
    uint32_t sb = (uint32_t)__cvta_generic_to_shared(dsm);

    const int b = blockIdx.z, hh = blockIdx.y;
    const int q0 = blockIdx.x * 256;
    const int t = threadIdx.x, lane = t & 31, w = t >> 5;
    const int wq = w * 16;
    const int bh = b * 12 + hh;
    const int ho = hh * HDIM;
    const size_t tok0 = (size_t)b * 1024 + q0;
    const int kg0 = b * 1024;

    const uint32_t Qb = sb;            // 256 x 128B = 32KB
    const uint32_t Bb = sb + 32768;    // 3 stages x 16KB

    // prologue: Q + ktile0 (group 0), ktile1 (group 1)
#pragma unroll
    for (int i = 0; i < 4; i++) {
        int idx = t + 512 * i;
        int r = idx >> 3, c = idx & 7;
        cp16(sw(Qb, r, c), qf + (tok0 + r) * DMODEL + ho + c * 8);
    }
    {
        int r = t >> 3, c = t & 7;   // 512 threads = 64 rows x 8 chunks
        cp16(sw(Bb, r, c),        kf + (size_t)(kg0 + r) * DMODEL + ho + c * 8);
        cp16(sw(Bb + 8192, r, c), vt + ((size_t)(bh * 64 + r)) * 1024 + c * 8);
    }
    cp_commit();
    {
        int r = t >> 3, c = t & 7;
        cp16(sw(Bb + AT_BUF, r, c),        kf + (size_t)(kg0 + 64 + r) * DMODEL + ho + c * 8);
        cp16(sw(Bb + AT_BUF + 8192, r, c), vt + ((size_t)(bh * 64 + r)) * 1024 + 64 + c * 8);
    }
    cp_commit();

    float oacc[8][4] = {};
    float rs0 = 0.f, rs1 = 0.f;
    uint32_t af[4][4];

    for (int kt = 0; kt < 16; kt++) {
        if (kt < 15) cp_wait1(); else cp_wait0();
        __syncthreads();

        if (kt + 2 < 16) {
            uint32_t nb = Bb + (uint32_t)((kt + 2) % 3) * AT_BUF;
            int kg = kg0 + (kt + 2) * 64;
            int r = t >> 3, c = t & 7;
            cp16(sw(nb, r, c),        kf + (size_t)(kg + r) * DMODEL + ho + c * 8);
            cp16(sw(nb + 8192, r, c), vt + ((size_t)(bh * 64 + r)) * 1024 + (kt + 2) * 64 + c * 8);
            cp_commit();
        }

        uint32_t cb = Bb + (uint32_t)(kt % 3) * AT_BUF;

        if (kt == 0) {
#pragma unroll
            for (int ks = 0; ks < 4; ks++) {
                int r = wq + (lane & 15);
                int c = ks * 2 + (lane >> 4);
                ldsm4(af[ks], sw(Qb, r, c));
            }
        }

        float sacc[8][4] = {};
#pragma unroll
        for (int kp = 0; kp < 2; kp++) {
            uint32_t bf[8][4];
#pragma unroll
            for (int j = 0; j < 8; j++) {
                int r = j * 8 + (lane & 7);
                int c = kp * 4 + ((lane >> 3) & 3);
                ldsm4(bf[j], sw(cb, r, c));
            }
#pragma unroll
            for (int s = 0; s < 2; s++)
#pragma unroll
                for (int j = 0; j < 8; j++)
                    mma_f16(sacc[j], af[kp * 2 + s], &bf[j][s * 2]);
        }

        uint32_t pa[4][4];
#pragma unroll
        for (int j = 0; j < 8; j++) {
            float e0 = __expf(sacc[j][0]);
            float e1 = __expf(sacc[j][1]);
            float e2 = __expf(sacc[j][2]);
            float e3 = __expf(sacc[j][3]);
            rs0 += e0 + e1;
            rs1 += e2 + e3;
            pa[j >> 1][(j & 1) * 2 + 0] = f16x2(e1, e0);
            pa[j >> 1][(j & 1) * 2 + 1] = f16x2(e3, e2);
        }

        uint32_t vb0 = cb + 8192;
#pragma unroll
        for (int kp = 0; kp < 2; kp++) {
            uint32_t vb[8][4];
#pragma unroll
            for (int j = 0; j < 8; j++) {
                int r = j * 8 + (lane & 7);
                int c = kp * 4 + ((lane >> 3) & 3);
                ldsm4(vb[j], sw(vb0, r, c));
            }
#pragma unroll
            for (int s = 0; s < 2; s++)
#pragma unroll
                for (int j = 0; j < 8; j++)
                    mma_f16(oacc[j], pa[kp * 2 + s], &vb[j][s * 2]);
        }
    }

    rs0 += __shfl_xor_sync(0xffffffffu, rs0, 1);
    rs0 += __shfl_xor_sync(0xffffffffu, rs0, 2);
    rs1 += __shfl_xor_sync(0xffffffffu, rs1, 1);
    rs1 += __shfl_xor_sync(0xffffffffu, rs1, 2);
    float inv0 = 1.0f / rs0, inv1 = 1.0f / rs1;

    size_t row0 = tok0 + wq + (lane >> 2);
    size_t row1 = row0 + 8;
#pragma unroll
    for (int j = 0; j < 8; j++) {
        int col = ho + j * 8 + 2 * (lane & 3);
        size_t o0 = row0 * DMODEL + col;
        size_t o1 = row1 * DMODEL + col;
        float2 x0 = *(const float2*)(x + o0);
        float2 x1v = *(const float2*)(x + o1);
        float2 r0 = { oacc[j][0] * inv0 + x0.x,  oacc[j][1] * inv0 + x0.y };
        float2 r1 = { oacc[j][2] * inv1 + x1v.x, oacc[j][3] * inv1 + x1v.y };
        *(float2*)(out + o0) = r0;
        *(float2*)(out + o1) = r1;
    }
}

// ---------------- HMMA plain-f16 GEMM: 256x128 tile, 3-stage, single sync/iter ----------------
#define GA_B   32768
#define GB_B   16384
#define GST_B  (GA_B + GB_B)

__device__ __forceinline__ void load_tile2(uint32_t sb,
    const __half* __restrict__ Ah, const __half* __restrict__ Bh,
    int m0, int n0, int K, int ic, int t)
{
#pragma unroll
    for (int i = 0; i < 8; i++) {
        int idx = t + 256 * i;
        int row = idx >> 3, ch = idx & 7;
        cp16(sw(sb, row, ch), Ah + (size_t)(m0 + row) * K + ic * 64 + ch * 8);
    }
#pragma unroll
    for (int i = 0; i < 4; i++) {
        int idx = t + 256 * i;
        int row = idx >> 3, ch = idx & 7;
        cp16(sw(sb + GA_B, row, ch), Bh + (size_t)(n0 + row) * K + ic * 64 + ch * 8);
    }
}

template<int MODE>
__global__ void __launch_bounds__(256, 1)
gemm_hmma_kernel(const __half* __restrict__ Ah, const __half* __restrict__ Bh,
                 const float* __restrict__ bias, const float* __restrict__ resid,
                 void* __restrict__ outp, int N, int K)
{
    extern __shared__ char dsm[];
    uint32_t smem_u32 = (uint32_t)__cvta_generic_to_shared(dsm);
    uint32_t base = (smem_u32 + 127) & ~127u;

    const int t = threadIdx.x;
    const int lane = t & 31, wid = t >> 5;
    const int m0 = blockIdx.y * 256, n0 = blockIdx.x * 128;
    const int warp_m = (wid >> 1) * 64, warp_n = (wid & 1) * 64;

    float acc[4][8][4] = {};
    const int NC = K >> 6;   // >= 12 always

    load_tile2(base,         Ah, Bh, m0, n0, K, 0, t);
    cp_commit();
    load_tile2(base + GST_B, Ah, Bh, m0, n0, K, 1, t);
    cp_commit();

    for (int ic = 0; ic < NC; ic++) {
        if (ic + 1 < NC) cp_wait1(); else cp_wait0();
        __syncthreads();

        if (ic + 2 < NC) {
            load_tile2(base + (uint32_t)((ic + 2) % 3) * GST_B, Ah, Bh, m0, n0, K, ic + 2, t);
            cp_commit();
        }

        uint32_t cb = base + (uint32_t)(ic % 3) * GST_B;
        uint32_t Ahb = cb, Bhb = cb + GA_B;
#pragma unroll
        for (int kp2 = 0; kp2 < 2; kp2++) {
            uint32_t ah[4][2][4];
#pragma unroll
            for (int mt = 0; mt < 4; mt++)
#pragma unroll
                for (int ks = 0; ks < 2; ks++) {
                    int row = warp_m + mt * 16 + (lane & 15);
                    int ch  = kp2 * 4 + ks * 2 + (lane >> 4);
                    ldsm4(ah[mt][ks], sw(Ahb, row, ch));
                }
#pragma unroll
            for (int np = 0; np < 4; np++) {
                uint32_t bh[2][4];
#pragma unroll
                for (int j = 0; j < 2; j++) {
                    int row = warp_n + (np * 2 + j) * 8 + (lane & 7);
                    int ch  = kp2 * 4 + ((lane >> 3) & 3);
                    ldsm4(bh[j], sw(Bhb, row, ch));
                }
#pragma unroll
                for (int ks = 0; ks < 2; ks++)
#pragma unroll
                    for (int mt = 0; mt < 4; mt++)
#pragma unroll
                        for (int j = 0; j < 2; j++)
                            mma_f16(acc[mt][np * 2 + j], ah[mt][ks], &bh[j][ks * 2]);
            }
        }
    }

    int rbase = m0 + warp_m + (lane >> 2);
    int cbase = n0 + warp_n + (lane & 3) * 2;
#pragma unroll
    for (int mt = 0; mt < 4; mt++)
#pragma unroll
        for (int nt = 0; nt < 8; nt++)
#pragma unroll
            for (int hh = 0; hh < 2; hh++) {
                int row = rbase + mt * 16 + hh * 8;
                int col = cbase + nt * 8;
                float v0 = acc[mt][nt][hh * 2 + 0] + bias[col];
                float v1 = acc[mt][nt][hh * 2 + 1] + bias[col + 1];
                size_t off = (size_t)row * N + col;
                if (MODE == 1) {
                    v0 = 0.5f * v0 * (1.0f + erff(v0 * 0.70710678118654752f));
                    v1 = 0.5f * v1 * (1.0f + erff(v1 * 0.70710678118654752f));
                    ((uint32_t*)outp)[off >> 1] = f16x2(v1, v0);
                } else {
                    const float2 rr = *(const float2*)(resid + off);
                    float2 ov = { v0 + rr.x, v1 + rr.y };
                    *(float2*)((float*)outp + off) = ov;
                }
            }
}

// ---------------- launch ----------------
extern "C" void kernel_launch(void* const* d_in, const int* in_sizes, int n_in,
                              void* d_out, int out_size)
{
    const float* x    = (const float*)d_in[0];
    const float* ln1g = (const float*)d_in[1];
    const float* ln1b = (const float*)d_in[2];
    const float* Wq   = (const float*)d_in[3];
    const float* bq   = (const float*)d_in[4];
    const float* Wk   = (const float*)d_in[5];
    const float* bk   = (const float*)d_in[6];
    const float* Wv   = (const float*)d_in[7];
    const float* bv   = (const float*)d_in[8];
    const float* ln2g = (const float*)d_in[9];
    const float* ln2b = (const float*)d_in[10];
    const float* W1   = (const float*)d_in[11];
    const float* b1   = (const float*)d_in[12];
    const float* W2   = (const float*)d_in[13];
    const float* b2   = (const float*)d_in[14];
    float* out = (float*)d_out;

    float* x1;
    __half *lnx, *lnh, *qf, *kf, *vt, *acth, *w1h, *w2h, *wqkv;
    cudaGetSymbolAddress((void**)&lnx,  g_lnx);
    cudaGetSymbolAddress((void**)&lnh,  g_lnh);
    cudaGetSymbolAddress((void**)&qf,   g_qf);
    cudaGetSymbolAddress((void**)&kf,   g_kf);
    cudaGetSymbolAddress((void**)&vt,   g_vt);
    cudaGetSymbolAddress((void**)&x1,   g_x1);
    cudaGetSymbolAddress((void**)&acth, g_acth);
    cudaGetSymbolAddress((void**)&w1h,  g_w1h);
    cudaGetSymbolAddress((void**)&w2h,  g_w2h);
    cudaGetSymbolAddress((void**)&wqkv, g_wqkv);

    const int ATTN_SMEM = 32768 + 3 * AT_BUF;   // 81920
    cudaFuncSetAttribute((const void*)attn_mma_kernel,
                         cudaFuncAttributeMaxDynamicSharedMemorySize, ATTN_SMEM);
    const int GEMM_SMEM = 3 * GST_B + 256;      // 147712
    cudaFuncSetAttribute(gemm_hmma_kernel<1>,
                         cudaFuncAttributeMaxDynamicSharedMemorySize, GEMM_SMEM);
    cudaFuncSetAttribute(gemm_hmma_kernel<2>,
                         cudaFuncAttributeMaxDynamicSharedMemorySize, GEMM_SMEM);
    cudaFuncSetAttribute((const void*)qkv_mma_kernel,
                         cudaFuncAttributeMaxDynamicSharedMemorySize, QKV_SMEM);

    convert_w_kernel<<<(DMLP * DMODEL + 255) / 256, 256>>>(W1, w1h, DMLP * DMODEL);
    convert_w_kernel<<<(DMODEL * DMLP + 255) / 256, 256>>>(W2, w2h, DMODEL * DMLP);
    convert_wqkv_kernel<<<(NHEAD * HDIM * HDIM + 255) / 256, 256>>>(Wq, Wk, Wv, wqkv);

    // 1) LN1 -> f16
    ln_f16_kernel<<<TOKENS, 256>>>(x, ln1g, ln1b, lnx);
    // 2) HMMA QKV
    qkv_mma_kernel<<<dim3(TOKENS / 128, NHEAD), 256, QKV_SMEM>>>(
        lnx, wqkv, bq, bk, bv, qf, kf, vt);
    // 3) HMMA attention + residual -> x1 (512 threads, 256 queries/CTA)
    attn_mma_kernel<<<dim3(SEQ / 256, NHEAD, BATCH), 512, ATTN_SMEM>>>(qf, kf, vt, x, x1);
    // 4) LN2 -> f16
    ln_f16_kernel<<<TOKENS, 256>>>(x1, ln2g, ln2b, lnh);
    // 5) MLP up + GELU -> act f16
    gemm_hmma_kernel<1><<<dim3(DMLP / 128, TOKENS / 256), 256, GEMM_SMEM>>>(
        lnh, w1h, b1, nullptr, (void*)acth, DMLP, DMODEL);
    // 6) MLP down + bias + residual -> out
    gemm_hmma_kernel<2><<<dim3(DMODEL / 128, TOKENS / 256), 256, GEMM_SMEM>>>(
        acth, w2h, b2, x1, (void*)out, DMODEL, DMLP);
}

// round 13
// speedup vs baseline: 1.0203x; 1.0203x over previous
#include <cuda_runtime.h>
#include <cuda_bf16.h>
#include <cuda_fp16.h>
#include <math.h>
#include <stdint.h>

#define TOKENS 16384
#define DMODEL 768
#define NHEAD  12
#define HDIM   64
#define DMLP   3072
#define SEQ    1024
#define BATCH  16

// ---------------- scratch (device globals; no cudaMalloc allowed) ----------------
__device__ __half g_lnx [TOKENS * DMODEL];   // LN1 out f16 (qkv input)
__device__ __half g_lnh [TOKENS * DMODEL];   // LN2 out f16
__device__ __half g_qf  [TOKENS * DMODEL];   // q f16, pre-scaled by 0.125 [tok][h*64+d]
__device__ __half g_kf  [TOKENS * DMODEL];   // k f16
__device__ __half g_vt  [TOKENS * DMODEL];   // V^T f16: [(b*12+h)*64+d][1024]
__device__ float  g_x1  [TOKENS * DMODEL];   // x + attn
__device__ __half g_acth[TOKENS * DMLP];     // GELU out f16
__device__ __half g_w1h [DMLP * DMODEL];     // W1 f16
__device__ __half g_w2h [DMODEL * DMLP];     // W2 f16
__device__ __half g_wqkv[3 * NHEAD * HDIM * HDIM];  // Wq|Wk|Wv f16

// ---------------- PTX helpers (portable sm_80-class only) ----------------
__device__ __forceinline__ void cp16(uint32_t s, const void* g) {
    asm volatile("cp.async.cg.shared.global [%0], [%1], 16;" :: "r"(s), "l"(g));
}
__device__ __forceinline__ void cp_commit() { asm volatile("cp.async.commit_group;" ::: "memory"); }
__device__ __forceinline__ void cp_wait1()  { asm volatile("cp.async.wait_group 1;" ::: "memory"); }
__device__ __forceinline__ void cp_wait0()  { asm volatile("cp.async.wait_group 0;" ::: "memory"); }

__device__ __forceinline__ void ldsm4(uint32_t* r, uint32_t addr) {
    asm volatile("ldmatrix.sync.aligned.m8n8.x4.shared.b16 {%0,%1,%2,%3}, [%4];"
                 : "=r"(r[0]), "=r"(r[1]), "=r"(r[2]), "=r"(r[3]) : "r"(addr));
}
__device__ __forceinline__ void mma_f16(float* d, const uint32_t* a, const uint32_t* b) {
    asm("mma.sync.aligned.m16n8k16.row.col.f32.f16.f16.f32 "
        "{%0,%1,%2,%3}, {%4,%5,%6,%7}, {%8,%9}, {%0,%1,%2,%3};"
        : "+f"(d[0]), "+f"(d[1]), "+f"(d[2]), "+f"(d[3])
        : "r"(a[0]), "r"(a[1]), "r"(a[2]), "r"(a[3]), "r"(b[0]), "r"(b[1]));
}
__device__ __forceinline__ uint32_t f16x2(float hi, float lo) {
    uint32_t u;
    asm("cvt.rn.f16x2.f32 %0, %1, %2;" : "=r"(u) : "f"(hi), "f"(lo));
    return u;
}

// ---------------- LayerNorm (f16 out) ----------------
__global__ void ln_f16_kernel(const float* __restrict__ x, const float* __restrict__ g,
                              const float* __restrict__ b, __half* __restrict__ oh)
{
    int tok = blockIdx.x;
    int t = threadIdx.x;
    const float* xr = x + (size_t)tok * DMODEL;
    float v0 = xr[t], v1 = xr[t + 256], v2 = xr[t + 512];
    float s = v0 + v1 + v2;
    __shared__ float red[8];
#pragma unroll
    for (int o = 16; o > 0; o >>= 1) s += __shfl_xor_sync(0xffffffffu, s, o);
    if ((t & 31) == 0) red[t >> 5] = s;
    __syncthreads();
    float tot = 0.f;
#pragma unroll
    for (int i = 0; i < 8; i++) tot += red[i];
    float mu = tot * (1.0f / DMODEL);
    float d0 = v0 - mu, d1 = v1 - mu, d2 = v2 - mu;
    float sq = d0 * d0 + d1 * d1 + d2 * d2;
#pragma unroll
    for (int o = 16; o > 0; o >>= 1) sq += __shfl_xor_sync(0xffffffffu, sq, o);
    __syncthreads();
    if ((t & 31) == 0) red[t >> 5] = sq;
    __syncthreads();
    float vs = 0.f;
#pragma unroll
    for (int i = 0; i < 8; i++) vs += red[i];
    float rs = rsqrtf(vs * (1.0f / DMODEL) + 1e-5f);
    size_t base = (size_t)tok * DMODEL;
    oh[base + t]       = __float2half(d0 * rs * g[t]       + b[t]);
    oh[base + t + 256] = __float2half(d1 * rs * g[t + 256] + b[t + 256]);
    oh[base + t + 512] = __float2half(d2 * rs * g[t + 512] + b[t + 512]);
}

// ---------------- weight conversions ----------------
__global__ void convert_w_kernel(const float* __restrict__ W, __half* __restrict__ wh, int n)
{
    int i = blockIdx.x * 256 + threadIdx.x;
    if (i < n) wh[i] = __float2half(W[i]);
}
__global__ void convert_wqkv_kernel(const float* __restrict__ Wq, const float* __restrict__ Wk,
                                    const float* __restrict__ Wv, __half* __restrict__ o)
{
    int i = blockIdx.x * 256 + threadIdx.x;
    const int n = NHEAD * HDIM * HDIM;
    if (i < n) {
        o[i]         = __float2half(Wq[i]);
        o[n + i]     = __float2half(Wk[i]);
        o[2 * n + i] = __float2half(Wv[i]);
    }
}

// ---------------- shared swizzle: 128B rows, 8 x 16B chunks ----------------
__device__ __forceinline__ uint32_t sw(uint32_t b, int row, int ch) {
    return b + (uint32_t)(row * 128) + (uint32_t)((ch ^ (row & 7)) << 4);
}

// ---------------- HMMA QKV: per-CTA 128 tokens x one head ----------------
#define QX_OFF  0
#define QW_OFF  16384
#define QV_OFF  (16384 + 3 * 8192)
#define QKV_SMEM (QV_OFF + 64 * 272)

__global__ void __launch_bounds__(256, 1) qkv_mma_kernel(
    const __half* __restrict__ lnx, const __half* __restrict__ wqkv,
    const float* __restrict__ bq, const float* __restrict__ bk, const float* __restrict__ bv,
    __half* __restrict__ qf, __half* __restrict__ kf, __half* __restrict__ vt)
{
    extern __shared__ char dsm[];
    uint32_t sb = (uint32_t)__cvta_generic_to_shared(dsm);
    const int hh = blockIdx.y;
    const int t0 = blockIdx.x * 128;
    const int t = threadIdx.x, lane = t & 31, w = t >> 5;
    const int ho = hh * HDIM;
    const int bh = (t0 >> 10) * 12 + hh;

#pragma unroll
    for (int i = 0; i < 4; i++) {
        int idx = t + 256 * i;
        int r = idx >> 3, c = idx & 7;
        cp16(sw(sb + QX_OFF, r, c), lnx + (size_t)(t0 + r) * DMODEL + ho + c * 8);
    }
#pragma unroll
    for (int m = 0; m < 3; m++)
#pragma unroll
        for (int i = 0; i < 2; i++) {
            int idx = t + 256 * i;
            int r = idx >> 3, c = idx & 7;
            cp16(sw(sb + QW_OFF + m * 8192, r, c),
                 wqkv + (size_t)(m * NHEAD + hh) * 4096 + r * 64 + c * 8);
        }
    cp_commit();
    cp_wait0();
    __syncthreads();

    uint32_t af[4][4];
#pragma unroll
    for (int ks = 0; ks < 4; ks++) {
        int r = w * 16 + (lane & 15);
        int c = ks * 2 + (lane >> 4);
        ldsm4(af[ks], sw(sb + QX_OFF, r, c));
    }

    const float* biases[3] = { bq + ho, bk + ho, bv + ho };

#pragma unroll
    for (int m = 0; m < 3; m++) {
        float acc[8][4] = {};
        uint32_t wb0 = sb + QW_OFF + m * 8192;
#pragma unroll
        for (int kp = 0; kp < 2; kp++) {
            uint32_t bf[8][4];
#pragma unroll
            for (int j = 0; j < 8; j++) {
                int r = j * 8 + (lane & 7);
                int c = kp * 4 + ((lane >> 3) & 3);
                ldsm4(bf[j], sw(wb0, r, c));
            }
#pragma unroll
            for (int s = 0; s < 2; s++)
#pragma unroll
                for (int j = 0; j < 8; j++)
                    mma_f16(acc[j], af[kp * 2 + s], &bf[j][s * 2]);
        }
        const float* bias = biases[m];
        int r0 = w * 16 + (lane >> 2);
        int cb = 2 * (lane & 3);
        if (m < 2) {
            __half* dst = (m == 0) ? qf : kf;
            float scale = (m == 0) ? 0.125f : 1.0f;
#pragma unroll
            for (int j = 0; j < 8; j++)
#pragma unroll
                for (int h2 = 0; h2 < 2; h2++) {
                    int col = cb + j * 8;
                    int row = t0 + r0 + h2 * 8;
                    float v0 = (acc[j][h2 * 2 + 0] + bias[col])     * scale;
                    float v1 = (acc[j][h2 * 2 + 1] + bias[col + 1]) * scale;
                    *(uint32_t*)(dst + (size_t)row * DMODEL + ho + col) = f16x2(v1, v0);
                }
        } else {
#pragma unroll
            for (int j = 0; j < 8; j++)
#pragma unroll
                for (int h2 = 0; h2 < 2; h2++) {
                    int col = cb + j * 8;
                    int rl  = r0 + h2 * 8;
                    float v0 = acc[j][h2 * 2 + 0] + bias[col];
                    float v1 = acc[j][h2 * 2 + 1] + bias[col + 1];
                    *(__half*)(dsm + QV_OFF + col * 272 + rl * 2)       = __float2half(v0);
                    *(__half*)(dsm + QV_OFF + (col + 1) * 272 + rl * 2) = __float2half(v1);
                }
        }
    }
    __syncthreads();
    int pos0 = t0 & 1023;
#pragma unroll
    for (int i = 0; i < 4; i++) {
        int idx = t + 256 * i;
        int o = idx >> 4, q16 = idx & 15;
        uint4 val = *(const uint4*)(dsm + QV_OFF + o * 272 + q16 * 16);
        *(uint4*)(vt + ((size_t)(bh * 64 + o)) * 1024 + pos0 + q16 * 8) = val;
    }
}

// ---------------- HMMA flash attention (R11 structure, 2 CTAs/SM) ----------------
#define AT_BUF 16384

__global__ void __launch_bounds__(256, 2) attn_mma_kernel(
    const __half* __restrict__ qf, const __half* __restrict__ kf,
    const __half* __restrict__ vt,
    const float* __restrict__ x, float* __restrict__ out)
{
    extern __shared__ char dsm[];
    uint32_t sb = (uint32_t)__cvta_generic_to_shared(dsm);

    const int b = blockIdx.z, hh = blockIdx.y;
    const int q0 = blockIdx.x * 128;
    const int t = threadIdx.x, lane = t & 31, w = t >> 5;
    const int wq = w * 16;
    const int bh = b * 12 + hh;
    const int ho = hh * HDIM;
    const size_t tok0 = (size_t)b * 1024 + q0;

    const uint32_t Qb = sb;
    const uint32_t Bb = sb + 16384;

#pragma unroll
    for (int i = 0; i < 4; i++) {
        int idx = t + 256 * i;
        int r = idx >> 3, c = idx & 7;
        cp16(sw(Qb, r, c), qf + (tok0 + r) * DMODEL + ho + c * 8);
    }
    {
        int kg0 = b * 1024;
#pragma unroll
        for (int i = 0; i < 2; i++) {
            int idx = t + 256 * i;
            int r = idx >> 3, c = idx & 7;
            cp16(sw(Bb, r, c),        kf + (size_t)(kg0 + r) * DMODEL + ho + c * 8);
            cp16(sw(Bb + 8192, r, c), vt + ((size_t)(bh * 64 + r)) * 1024 + c * 8);
        }
    }
    cp_commit();

    float oacc[8][4] = {};
    float rs0 = 0.f, rs1 = 0.f;
    uint32_t af[4][4];

    for (int kt = 0; kt < 16; kt++) {
        if (kt + 1 < 16) {
            uint32_t nb = Bb + (uint32_t)((kt + 1) & 1) * AT_BUF;
            int kg = b * 1024 + (kt + 1) * 64;
#pragma unroll
            for (int i = 0; i < 2; i++) {
                int idx = t + 256 * i;
                int r = idx >> 3, c = idx & 7;
                cp16(sw(nb, r, c),        kf + (size_t)(kg + r) * DMODEL + ho + c * 8);
                cp16(sw(nb + 8192, r, c), vt + ((size_t)(bh * 64 + r)) * 1024 + (kt + 1) * 64 + c * 8);
            }
            cp_commit();
            cp_wait1();
        } else {
            cp_wait0();
        }
        __syncthreads();

        uint32_t cb = Bb + (uint32_t)(kt & 1) * AT_BUF;

        if (kt == 0) {
#pragma unroll
            for (int ks = 0; ks < 4; ks++) {
                int r = wq + (lane & 15);
                int c = ks * 2 + (lane >> 4);
                ldsm4(af[ks], sw(Qb, r, c));
            }
        }

        float sacc[8][4] = {};
#pragma unroll
        for (int kp = 0; kp < 2; kp++) {
            uint32_t bf[8][4];
#pragma unroll
            for (int j = 0; j < 8; j++) {
                int r = j * 8 + (lane & 7);
                int c = kp * 4 + ((lane >> 3) & 3);
                ldsm4(bf[j], sw(cb, r, c));
            }
#pragma unroll
            for (int s = 0; s < 2; s++)
#pragma unroll
                for (int j = 0; j < 8; j++)
                    mma_f16(sacc[j], af[kp * 2 + s], &bf[j][s * 2]);
        }

        uint32_t pa[4][4];
#pragma unroll
        for (int j = 0; j < 8; j++) {
            float e0 = __expf(sacc[j][0]);
            float e1 = __expf(sacc[j][1]);
            float e2 = __expf(sacc[j][2]);
            float e3 = __expf(sacc[j][3]);
            rs0 += e0 + e1;
            rs1 += e2 + e3;
            pa[j >> 1][(j & 1) * 2 + 0] = f16x2(e1, e0);
            pa[j >> 1][(j & 1) * 2 + 1] = f16x2(e3, e2);
        }

        uint32_t vb0 = cb + 8192;
#pragma unroll
        for (int kp = 0; kp < 2; kp++) {
            uint32_t vb[8][4];
#pragma unroll
            for (int j = 0; j < 8; j++) {
                int r = j * 8 + (lane & 7);
                int c = kp * 4 + ((lane >> 3) & 3);
                ldsm4(vb[j], sw(vb0, r, c));
            }
#pragma unroll
            for (int s = 0; s < 2; s++)
#pragma unroll
                for (int j = 0; j < 8; j++)
                    mma_f16(oacc[j], pa[kp * 2 + s], &vb[j][s * 2]);
        }
        __syncthreads();
    }

    rs0 += __shfl_xor_sync(0xffffffffu, rs0, 1);
    rs0 += __shfl_xor_sync(0xffffffffu, rs0, 2);
    rs1 += __shfl_xor_sync(0xffffffffu, rs1, 1);
    rs1 += __shfl_xor_sync(0xffffffffu, rs1, 2);
    float inv0 = 1.0f / rs0, inv1 = 1.0f / rs1;

    size_t row0 = tok0 + wq + (lane >> 2);
    size_t row1 = row0 + 8;
#pragma unroll
    for (int j = 0; j < 8; j++) {
        int col = ho + j * 8 + 2 * (lane & 3);
        size_t o0 = row0 * DMODEL + col;
        size_t o1 = row1 * DMODEL + col;
        float2 x0 = *(const float2*)(x + o0);
        float2 x1v = *(const float2*)(x + o1);
        float2 r0 = { oacc[j][0] * inv0 + x0.x,  oacc[j][1] * inv0 + x0.y };
        float2 r1 = { oacc[j][2] * inv1 + x1v.x, oacc[j][3] * inv1 + x1v.y };
        *(float2*)(out + o0) = r0;
        *(float2*)(out + o1) = r1;
    }
}

// ---------------- HMMA plain-f16 GEMM: 256x128 CTA tile, 64x64 warp tile (R11) ----------------
#define GA_B   32768
#define GB_B   16384
#define GST_B  (GA_B + GB_B)

__device__ __forceinline__ void load_tile2(uint32_t sb,
    const __half* __restrict__ Ah, const __half* __restrict__ Bh,
    int m0, int n0, int K, int ic, int t)
{
#pragma unroll
    for (int i = 0; i < 8; i++) {
        int idx = t + 256 * i;
        int row = idx >> 3, ch = idx & 7;
        cp16(sw(sb, row, ch), Ah + (size_t)(m0 + row) * K + ic * 64 + ch * 8);
    }
#pragma unroll
    for (int i = 0; i < 4; i++) {
        int idx = t + 256 * i;
        int row = idx >> 3, ch = idx & 7;
        cp16(sw(sb + GA_B, row, ch), Bh + (size_t)(n0 + row) * K + ic * 64 + ch * 8);
    }
}

template<int MODE>
__global__ void __launch_bounds__(256, 1)
gemm_hmma_kernel(const __half* __restrict__ Ah, const __half* __restrict__ Bh,
                 const float* __restrict__ bias, const float* __restrict__ resid,
                 void* __restrict__ outp, int N, int K)
{
    extern __shared__ char dsm[];
    uint32_t smem_u32 = (uint32_t)__cvta_generic_to_shared(dsm);
    uint32_t base = (smem_u32 + 127) & ~127u;

    const int t = threadIdx.x;
    const int lane = t & 31, wid = t >> 5;
    const int m0 = blockIdx.y * 256, n0 = blockIdx.x * 128;
    const int warp_m = (wid >> 1) * 64, warp_n = (wid & 1) * 64;

    float acc[4][8][4] = {};
    const int NC = K >> 6;

    load_tile2(base, Ah, Bh, m0, n0, K, 0, t);
    cp_commit();

    for (int ic = 0; ic < NC; ic++) {
        uint32_t cb = base + (uint32_t)(ic & 1) * GST_B;
        if (ic + 1 < NC) {
            load_tile2(base + (uint32_t)((ic + 1) & 1) * GST_B, Ah, Bh, m0, n0, K, ic + 1, t);
            cp_commit();
            cp_wait1();
        } else {
            cp_wait0();
        }
        __syncthreads();

        uint32_t Ahb = cb, Bhb = cb + GA_B;
#pragma unroll
        for (int kp2 = 0; kp2 < 2; kp2++) {
            uint32_t ah[4][2][4];
#pragma unroll
            for (int mt = 0; mt < 4; mt++)
#pragma unroll
                for (int ks = 0; ks < 2; ks++) {
                    int row = warp_m + mt * 16 + (lane & 15);
                    int ch  = kp2 * 4 + ks * 2 + (lane >> 4);
                    ldsm4(ah[mt][ks], sw(Ahb, row, ch));
                }
#pragma unroll
            for (int np = 0; np < 4; np++) {
                uint32_t bh[2][4];
#pragma unroll
                for (int j = 0; j < 2; j++) {
                    int row = warp_n + (np * 2 + j) * 8 + (lane & 7);
                    int ch  = kp2 * 4 + ((lane >> 3) & 3);
                    ldsm4(bh[j], sw(Bhb, row, ch));
                }
#pragma unroll
                for (int ks = 0; ks < 2; ks++)
#pragma unroll
                    for (int mt = 0; mt < 4; mt++)
#pragma unroll
                        for (int j = 0; j < 2; j++)
                            mma_f16(acc[mt][np * 2 + j], ah[mt][ks], &bh[j][ks * 2]);
            }
        }
        __syncthreads();
    }

    int rbase = m0 + warp_m + (lane >> 2);
    int cbase = n0 + warp_n + (lane & 3) * 2;
#pragma unroll
    for (int mt = 0; mt < 4; mt++)
#pragma unroll
        for (int nt = 0; nt < 8; nt++)
#pragma unroll
            for (int hh = 0; hh < 2; hh++) {
                int row = rbase + mt * 16 + hh * 8;
                int col = cbase + nt * 8;
                float v0 = acc[mt][nt][hh * 2 + 0] + bias[col];
                float v1 = acc[mt][nt][hh * 2 + 1] + bias[col + 1];
                size_t off = (size_t)row * N + col;
                if (MODE == 1) {
                    v0 = 0.5f * v0 * (1.0f + erff(v0 * 0.70710678118654752f));
                    v1 = 0.5f * v1 * (1.0f + erff(v1 * 0.70710678118654752f));
                    ((uint32_t*)outp)[off >> 1] = f16x2(v1, v0);
                } else {
                    const float2 rr = *(const float2*)(resid + off);
                    float2 ov = { v0 + rr.x, v1 + rr.y };
                    *(float2*)((float*)outp + off) = ov;
                }
            }
}

// ---------------- launch ----------------
extern "C" void kernel_launch(void* const* d_in, const int* in_sizes, int n_in,
                              void* d_out, int out_size)
{
    const float* x    = (const float*)d_in[0];
    const float* ln1g = (const float*)d_in[1];
    const float* ln1b = (const float*)d_in[2];
    const float* Wq   = (const float*)d_in[3];
    const float* bq   = (const float*)d_in[4];
    const float* Wk   = (const float*)d_in[5];
    const float* bk   = (const float*)d_in[6];
    const float* Wv   = (const float*)d_in[7];
    const float* bv   = (const float*)d_in[8];
    const float* ln2g = (const float*)d_in[9];
    const float* ln2b = (const float*)d_in[10];
    const float* W1   = (const float*)d_in[11];
    const float* b1   = (const float*)d_in[12];
    const float* W2   = (const float*)d_in[13];
    const float* b2   = (const float*)d_in[14];
    float* out = (float*)d_out;

    float* x1;
    __half *lnx, *lnh, *qf, *kf, *vt, *acth, *w1h, *w2h, *wqkv;
    cudaGetSymbolAddress((void**)&lnx,  g_lnx);
    cudaGetSymbolAddress((void**)&lnh,  g_lnh);
    cudaGetSymbolAddress((void**)&qf,   g_qf);
    cudaGetSymbolAddress((void**)&kf,   g_kf);
    cudaGetSymbolAddress((void**)&vt,   g_vt);
    cudaGetSymbolAddress((void**)&x1,   g_x1);
    cudaGetSymbolAddress((void**)&acth, g_acth);
    cudaGetSymbolAddress((void**)&w1h,  g_w1h);
    cudaGetSymbolAddress((void**)&w2h,  g_w2h);
    cudaGetSymbolAddress((void**)&wqkv, g_wqkv);

    const int ATTN_SMEM = 16384 + 2 * AT_BUF;   // 49152 (2 CTAs/SM fit)
    cudaFuncSetAttribute((const void*)attn_mma_kernel,
                         cudaFuncAttributeMaxDynamicSharedMemorySize, ATTN_SMEM);
    const int GEMM_SMEM = 2 * GST_B + 256;      // 98560
    cudaFuncSetAttribute(gemm_hmma_kernel<1>,
                         cudaFuncAttributeMaxDynamicSharedMemorySize, GEMM_SMEM);
    cudaFuncSetAttribute(gemm_hmma_kernel<2>,
                         cudaFuncAttributeMaxDynamicSharedMemorySize, GEMM_SMEM);
    cudaFuncSetAttribute((const void*)qkv_mma_kernel,
                         cudaFuncAttributeMaxDynamicSharedMemorySize, QKV_SMEM);

    convert_w_kernel<<<(DMLP * DMODEL + 255) / 256, 256>>>(W1, w1h, DMLP * DMODEL);
    convert_w_kernel<<<(DMODEL * DMLP + 255) / 256, 256>>>(W2, w2h, DMODEL * DMLP);
    convert_wqkv_kernel<<<(NHEAD * HDIM * HDIM + 255) / 256, 256>>>(Wq, Wk, Wv, wqkv);

    // 1) LN1 -> f16
    ln_f16_kernel<<<TOKENS, 256>>>(x, ln1g, ln1b, lnx);
    // 2) HMMA QKV
    qkv_mma_kernel<<<dim3(TOKENS / 128, NHEAD), 256, QKV_SMEM>>>(
        lnx, wqkv, bq, bk, bv, qf, kf, vt);
    // 3) HMMA attention + residual -> x1 (2 CTAs/SM)
    attn_mma_kernel<<<dim3(SEQ / 128, NHEAD, BATCH), 256, ATTN_SMEM>>>(qf, kf, vt, x, x1);
    // 4) LN2 -> f16
    ln_f16_kernel<<<TOKENS, 256>>>(x1, ln2g, ln2b, lnh);
    // 5) MLP up + GELU -> act f16
    gemm_hmma_kernel<1><<<dim3(DMLP / 128, TOKENS / 256), 256, GEMM_SMEM>>>(
        lnh, w1h, b1, nullptr, (void*)acth, DMLP, DMODEL);
    // 6) MLP down + bias + residual -> out
    gemm_hmma_kernel<2><<<dim3(DMODEL / 128, TOKENS / 256), 256, GEMM_SMEM>>>(
        acth, w2h, b2, x1, (void*)out, DMODEL, DMLP);
}

// round 14
// speedup vs baseline: 1.0496x; 1.0286x over previous
#include <cuda_runtime.h>
#include <cuda_bf16.h>
#include <cuda_fp16.h>
#include <math.h>
#include <stdint.h>

#define TOKENS 16384
#define DMODEL 768
#define NHEAD  12
#define HDIM   64
#define DMLP   3072
#define SEQ    1024
#define BATCH  16

// ---------------- scratch (device globals; no cudaMalloc allowed) ----------------
__device__ __half g_lnx [TOKENS * DMODEL];   // LN1 out f16 (qkv input)
__device__ __half g_lnh [TOKENS * DMODEL];   // LN2 out f16
__device__ __half g_qf  [TOKENS * DMODEL];   // q f16, pre-scaled by 0.125 [tok][h*64+d]
__device__ __half g_kf  [TOKENS * DMODEL];   // k f16
__device__ __half g_vt  [TOKENS * DMODEL];   // V^T f16: [(b*12+h)*64+d][1024]
__device__ float  g_x1  [TOKENS * DMODEL];   // x + attn
__device__ __half g_acth[TOKENS * DMLP];     // GELU out f16
__device__ __half g_w1h [DMLP * DMODEL];     // W1 f16
__device__ __half g_w2h [DMODEL * DMLP];     // W2 f16
__device__ __half g_wqkv[3 * NHEAD * HDIM * HDIM];  // Wq|Wk|Wv f16

// ---------------- PTX helpers (portable sm_80-class only) ----------------
__device__ __forceinline__ void cp16(uint32_t s, const void* g) {
    asm volatile("cp.async.cg.shared.global [%0], [%1], 16;" :: "r"(s), "l"(g));
}
__device__ __forceinline__ void cp_commit() { asm volatile("cp.async.commit_group;" ::: "memory"); }
__device__ __forceinline__ void cp_wait1()  { asm volatile("cp.async.wait_group 1;" ::: "memory"); }
__device__ __forceinline__ void cp_wait0()  { asm volatile("cp.async.wait_group 0;" ::: "memory"); }

__device__ __forceinline__ void ldsm4(uint32_t* r, uint32_t addr) {
    asm volatile("ldmatrix.sync.aligned.m8n8.x4.shared.b16 {%0,%1,%2,%3}, [%4];"
                 : "=r"(r[0]), "=r"(r[1]), "=r"(r[2]), "=r"(r[3]) : "r"(addr));
}
__device__ __forceinline__ void mma_f16(float* d, const uint32_t* a, const uint32_t* b) {
    asm("mma.sync.aligned.m16n8k16.row.col.f32.f16.f16.f32 "
        "{%0,%1,%2,%3}, {%4,%5,%6,%7}, {%8,%9}, {%0,%1,%2,%3};"
        : "+f"(d[0]), "+f"(d[1]), "+f"(d[2]), "+f"(d[3])
        : "r"(a[0]), "r"(a[1]), "r"(a[2]), "r"(a[3]), "r"(b[0]), "r"(b[1]));
}
__device__ __forceinline__ uint32_t f16x2(float hi, float lo) {
    uint32_t u;
    asm("cvt.rn.f16x2.f32 %0, %1, %2;" : "=r"(u) : "f"(hi), "f"(lo));
    return u;
}

// ---------------- LayerNorm (f16 out, float4 loads) ----------------
__global__ void ln_f16_kernel(const float* __restrict__ x, const float* __restrict__ g,
                              const float* __restrict__ b, __half* __restrict__ oh)
{
    int tok = blockIdx.x;
    int t = threadIdx.x;
    float4 v = make_float4(0.f, 0.f, 0.f, 0.f);
    if (t < 192) v = ((const float4*)(x + (size_t)tok * DMODEL))[t];
    float s = v.x + v.y + v.z + v.w;
    __shared__ float red[8];
#pragma unroll
    for (int o = 16; o > 0; o >>= 1) s += __shfl_xor_sync(0xffffffffu, s, o);
    if ((t & 31) == 0) red[t >> 5] = s;
    __syncthreads();
    float tot = 0.f;
#pragma unroll
    for (int i = 0; i < 8; i++) tot += red[i];
    float mu = tot * (1.0f / DMODEL);
    float d0 = v.x - mu, d1 = v.y - mu, d2 = v.z - mu, d3 = v.w - mu;
    float sq = (t < 192) ? (d0 * d0 + d1 * d1 + d2 * d2 + d3 * d3) : 0.f;
#pragma unroll
    for (int o = 16; o > 0; o >>= 1) sq += __shfl_xor_sync(0xffffffffu, sq, o);
    __syncthreads();
    if ((t & 31) == 0) red[t >> 5] = sq;
    __syncthreads();
    float vs = 0.f;
#pragma unroll
    for (int i = 0; i < 8; i++) vs += red[i];
    float rs = rsqrtf(vs * (1.0f / DMODEL) + 1e-5f);
    if (t < 192) {
        float4 g4 = ((const float4*)g)[t];
        float4 b4 = ((const float4*)b)[t];
        uint2 pk;
        pk.x = f16x2(d1 * rs * g4.y + b4.y, d0 * rs * g4.x + b4.x);
        pk.y = f16x2(d3 * rs * g4.w + b4.w, d2 * rs * g4.z + b4.z);
        ((uint2*)(oh + (size_t)tok * DMODEL))[t] = pk;
    }
}

// ---------------- weight conversions (W1+W2 merged) ----------------
__global__ void convert_w12_kernel(const float* __restrict__ W1, __half* __restrict__ w1h,
                                   const float* __restrict__ W2, __half* __restrict__ w2h)
{
    int i = blockIdx.x * 256 + threadIdx.x;
    const int n = DMLP * DMODEL;   // same size both ways
    if (i < n) {
        w1h[i] = __float2half(W1[i]);
        w2h[i] = __float2half(W2[i]);
    }
}
__global__ void convert_wqkv_kernel(const float* __restrict__ Wq, const float* __restrict__ Wk,
                                    const float* __restrict__ Wv, __half* __restrict__ o)
{
    int i = blockIdx.x * 256 + threadIdx.x;
    const int n = NHEAD * HDIM * HDIM;
    if (i < n) {
        o[i]         = __float2half(Wq[i]);
        o[n + i]     = __float2half(Wk[i]);
        o[2 * n + i] = __float2half(Wv[i]);
    }
}

// ---------------- shared swizzle: 128B rows, 8 x 16B chunks ----------------
__device__ __forceinline__ uint32_t sw(uint32_t b, int row, int ch) {
    return b + (uint32_t)(row * 128) + (uint32_t)((ch ^ (row & 7)) << 4);
}

// ---------------- HMMA QKV: per-CTA 128 tokens x one head (R11, proven) ----------------
#define QX_OFF  0
#define QW_OFF  16384
#define QV_OFF  (16384 + 3 * 8192)
#define QKV_SMEM (QV_OFF + 64 * 272)

__global__ void __launch_bounds__(256, 1) qkv_mma_kernel(
    const __half* __restrict__ lnx, const __half* __restrict__ wqkv,
    const float* __restrict__ bq, const float* __restrict__ bk, const float* __restrict__ bv,
    __half* __restrict__ qf, __half* __restrict__ kf, __half* __restrict__ vt)
{
    extern __shared__ char dsm[];
    uint32_t sb = (uint32_t)__cvta_generic_to_shared(dsm);
    const int hh = blockIdx.y;
    const int t0 = blockIdx.x * 128;
    const int t = threadIdx.x, lane = t & 31, w = t >> 5;
    const int ho = hh * HDIM;
    const int bh = (t0 >> 10) * 12 + hh;

#pragma unroll
    for (int i = 0; i < 4; i++) {
        int idx = t + 256 * i;
        int r = idx >> 3, c = idx & 7;
        cp16(sw(sb + QX_OFF, r, c), lnx + (size_t)(t0 + r) * DMODEL + ho + c * 8);
    }
#pragma unroll
    for (int m = 0; m < 3; m++)
#pragma unroll
        for (int i = 0; i < 2; i++) {
            int idx = t + 256 * i;
            int r = idx >> 3, c = idx & 7;
            cp16(sw(sb + QW_OFF + m * 8192, r, c),
                 wqkv + (size_t)(m * NHEAD + hh) * 4096 + r * 64 + c * 8);
        }
    cp_commit();
    cp_wait0();
    __syncthreads();

    uint32_t af[4][4];
#pragma unroll
    for (int ks = 0; ks < 4; ks++) {
        int r = w * 16 + (lane & 15);
        int c = ks * 2 + (lane >> 4);
        ldsm4(af[ks], sw(sb + QX_OFF, r, c));
    }

    const float* biases[3] = { bq + ho, bk + ho, bv + ho };

#pragma unroll
    for (int m = 0; m < 3; m++) {
        float acc[8][4] = {};
        uint32_t wb0 = sb + QW_OFF + m * 8192;
#pragma unroll
        for (int kp = 0; kp < 2; kp++) {
            uint32_t bf[8][4];
#pragma unroll
            for (int j = 0; j < 8; j++) {
                int r = j * 8 + (lane & 7);
                int c = kp * 4 + ((lane >> 3) & 3);
                ldsm4(bf[j], sw(wb0, r, c));
            }
#pragma unroll
            for (int s = 0; s < 2; s++)
#pragma unroll
                for (int j = 0; j < 8; j++)
                    mma_f16(acc[j], af[kp * 2 + s], &bf[j][s * 2]);
        }
        const float* bias = biases[m];
        int r0 = w * 16 + (lane >> 2);
        int cb = 2 * (lane & 3);
        if (m < 2) {
            __half* dst = (m == 0) ? qf : kf;
            float scale = (m == 0) ? 0.125f : 1.0f;
#pragma unroll
            for (int j = 0; j < 8; j++)
#pragma unroll
                for (int h2 = 0; h2 < 2; h2++) {
                    int col = cb + j * 8;
                    int row = t0 + r0 + h2 * 8;
                    float v0 = (acc[j][h2 * 2 + 0] + bias[col])     * scale;
                    float v1 = (acc[j][h2 * 2 + 1] + bias[col + 1]) * scale;
                    *(uint32_t*)(dst + (size_t)row * DMODEL + ho + col) = f16x2(v1, v0);
                }
        } else {
#pragma unroll
            for (int j = 0; j < 8; j++)
#pragma unroll
                for (int h2 = 0; h2 < 2; h2++) {
                    int col = cb + j * 8;
                    int rl  = r0 + h2 * 8;
                    float v0 = acc[j][h2 * 2 + 0] + bias[col];
                    float v1 = acc[j][h2 * 2 + 1] + bias[col + 1];
                    *(__half*)(dsm + QV_OFF + col * 272 + rl * 2)       = __float2half(v0);
                    *(__half*)(dsm + QV_OFF + (col + 1) * 272 + rl * 2) = __float2half(v1);
                }
        }
    }
    __syncthreads();
    int pos0 = t0 & 1023;
#pragma unroll
    for (int i = 0; i < 4; i++) {
        int idx = t + 256 * i;
        int o = idx >> 4, q16 = idx & 15;
        uint4 val = *(const uint4*)(dsm + QV_OFF + o * 272 + q16 * 16);
        *(uint4*)(vt + ((size_t)(bh * 64 + o)) * 1024 + pos0 + q16 * 8) = val;
    }
}

// ---------------- HMMA flash attention: 256 threads, 3-stage, single sync, 2 CTAs/SM ----------------
#define AT_BUF 16384   // per-stage: K 8KB + Vt 8KB

__global__ void __launch_bounds__(256, 2) attn_mma_kernel(
    const __half* __restrict__ qf, const __half* __restrict__ kf,
    const __half* __restrict__ vt,
    const float* __restrict__ x, float* __restrict__ out)
{
    extern __shared__ char dsm[];
    uint32_t sb = (uint32_t)__cvta_generic_to_shared(dsm);

    const int b = blockIdx.z, hh = blockIdx.y;
    const int q0 = blockIdx.x * 128;
    const int t = threadIdx.x, lane = t & 31, w = t >> 5;
    const int wq = w * 16;
    const int bh = b * 12 + hh;
    const int ho = hh * HDIM;
    const size_t tok0 = (size_t)b * 1024 + q0;
    const int kg0 = b * 1024;

    const uint32_t Qb = sb;            // 128 x 128B = 16KB
    const uint32_t Bb = sb + 16384;    // 3 stages x 16KB

    // prologue: Q + ktile0 (group 0), ktile1 (group 1)
#pragma unroll
    for (int i = 0; i < 4; i++) {
        int idx = t + 256 * i;
        int r = idx >> 3, c = idx & 7;
        cp16(sw(Qb, r, c), qf + (tok0 + r) * DMODEL + ho + c * 8);
    }
#pragma unroll
    for (int i = 0; i < 2; i++) {
        int idx = t + 256 * i;
        int r = idx >> 3, c = idx & 7;
        cp16(sw(Bb, r, c),        kf + (size_t)(kg0 + r) * DMODEL + ho + c * 8);
        cp16(sw(Bb + 8192, r, c), vt + ((size_t)(bh * 64 + r)) * 1024 + c * 8);
    }
    cp_commit();
#pragma unroll
    for (int i = 0; i < 2; i++) {
        int idx = t + 256 * i;
        int r = idx >> 3, c = idx & 7;
        cp16(sw(Bb + AT_BUF, r, c),        kf + (size_t)(kg0 + 64 + r) * DMODEL + ho + c * 8);
        cp16(sw(Bb + AT_BUF + 8192, r, c), vt + ((size_t)(bh * 64 + r)) * 1024 + 64 + c * 8);
    }
    cp_commit();

    float oacc[8][4] = {};
    float rs0 = 0.f, rs1 = 0.f;
    uint32_t af[4][4];

    for (int kt = 0; kt < 16; kt++) {
        if (kt < 15) cp_wait1(); else cp_wait0();
        __syncthreads();   // buffer kt ready; also proves (kt+2)%3's old readers done

        if (kt + 2 < 16) {
            uint32_t nb = Bb + (uint32_t)((kt + 2) % 3) * AT_BUF;
            int kg = kg0 + (kt + 2) * 64;
#pragma unroll
            for (int i = 0; i < 2; i++) {
                int idx = t + 256 * i;
                int r = idx >> 3, c = idx & 7;
                cp16(sw(nb, r, c),        kf + (size_t)(kg + r) * DMODEL + ho + c * 8);
                cp16(sw(nb + 8192, r, c), vt + ((size_t)(bh * 64 + r)) * 1024 + (kt + 2) * 64 + c * 8);
            }
            cp_commit();
        }

        uint32_t cb = Bb + (uint32_t)(kt % 3) * AT_BUF;

        if (kt == 0) {
#pragma unroll
            for (int ks = 0; ks < 4; ks++) {
                int r = wq + (lane & 15);
                int c = ks * 2 + (lane >> 4);
                ldsm4(af[ks], sw(Qb, r, c));
            }
        }

        float sacc[8][4] = {};
#pragma unroll
        for (int kp = 0; kp < 2; kp++) {
            uint32_t bf[8][4];
#pragma unroll
            for (int j = 0; j < 8; j++) {
                int r = j * 8 + (lane & 7);
                int c = kp * 4 + ((lane >> 3) & 3);
                ldsm4(bf[j], sw(cb, r, c));
            }
#pragma unroll
            for (int s = 0; s < 2; s++)
#pragma unroll
                for (int j = 0; j < 8; j++)
                    mma_f16(sacc[j], af[kp * 2 + s], &bf[j][s * 2]);
        }

        uint32_t pa[4][4];
#pragma unroll
        for (int j = 0; j < 8; j++) {
            float e0 = __expf(sacc[j][0]);
            float e1 = __expf(sacc[j][1]);
            float e2 = __expf(sacc[j][2]);
            float e3 = __expf(sacc[j][3]);
            rs0 += e0 + e1;
            rs1 += e2 + e3;
            pa[j >> 1][(j & 1) * 2 + 0] = f16x2(e1, e0);
            pa[j >> 1][(j & 1) * 2 + 1] = f16x2(e3, e2);
        }

        uint32_t vb0 = cb + 8192;
#pragma unroll
        for (int kp = 0; kp < 2; kp++) {
            uint32_t vb[8][4];
#pragma unroll
            for (int j = 0; j < 8; j++) {
                int r = j * 8 + (lane & 7);
                int c = kp * 4 + ((lane >> 3) & 3);
                ldsm4(vb[j], sw(vb0, r, c));
            }
#pragma unroll
            for (int s = 0; s < 2; s++)
#pragma unroll
                for (int j = 0; j < 8; j++)
                    mma_f16(oacc[j], pa[kp * 2 + s], &vb[j][s * 2]);
        }
    }

    rs0 += __shfl_xor_sync(0xffffffffu, rs0, 1);
    rs0 += __shfl_xor_sync(0xffffffffu, rs0, 2);
    rs1 += __shfl_xor_sync(0xffffffffu, rs1, 1);
    rs1 += __shfl_xor_sync(0xffffffffu, rs1, 2);
    float inv0 = 1.0f / rs0, inv1 = 1.0f / rs1;

    size_t row0 = tok0 + wq + (lane >> 2);
    size_t row1 = row0 + 8;
#pragma unroll
    for (int j = 0; j < 8; j++) {
        int col = ho + j * 8 + 2 * (lane & 3);
        size_t o0 = row0 * DMODEL + col;
        size_t o1 = row1 * DMODEL + col;
        float2 x0 = *(const float2*)(x + o0);
        float2 x1v = *(const float2*)(x + o1);
        float2 r0 = { oacc[j][0] * inv0 + x0.x,  oacc[j][1] * inv0 + x0.y };
        float2 r1 = { oacc[j][2] * inv1 + x1v.x, oacc[j][3] * inv1 + x1v.y };
        *(float2*)(out + o0) = r0;
        *(float2*)(out + o1) = r1;
    }
}

// ---------------- HMMA plain-f16 GEMM: 256x128 CTA tile, 64x64 warp tile (R11, proven) ----------------
#define GA_B   32768
#define GB_B   16384
#define GST_B  (GA_B + GB_B)

__device__ __forceinline__ void load_tile2(uint32_t sb,
    const __half* __restrict__ Ah, const __half* __restrict__ Bh,
    int m0, int n0, int K, int ic, int t)
{
#pragma unroll
    for (int i = 0; i < 8; i++) {
        int idx = t + 256 * i;
        int row = idx >> 3, ch = idx & 7;
        cp16(sw(sb, row, ch), Ah + (size_t)(m0 + row) * K + ic * 64 + ch * 8);
    }
#pragma unroll
    for (int i = 0; i < 4; i++) {
        int idx = t + 256 * i;
        int row = idx >> 3, ch = idx & 7;
        cp16(sw(sb + GA_B, row, ch), Bh + (size_t)(n0 + row) * K + ic * 64 + ch * 8);
    }
}

template<int MODE>
__global__ void __launch_bounds__(256, 1)
gemm_hmma_kernel(const __half* __restrict__ Ah, const __half* __restrict__ Bh,
                 const float* __restrict__ bias, const float* __restrict__ resid,
                 void* __restrict__ outp, int N, int K)
{
    extern __shared__ char dsm[];
    uint32_t smem_u32 = (uint32_t)__cvta_generic_to_shared(dsm);
    uint32_t base = (smem_u32 + 127) & ~127u;

    const int t = threadIdx.x;
    const int lane = t & 31, wid = t >> 5;
    const int m0 = blockIdx.y * 256, n0 = blockIdx.x * 128;
    const int warp_m = (wid >> 1) * 64, warp_n = (wid & 1) * 64;

    float acc[4][8][4] = {};
    const int NC = K >> 6;

    load_tile2(base, Ah, Bh, m0, n0, K, 0, t);
    cp_commit();

    for (int ic = 0; ic < NC; ic++) {
        uint32_t cb = base + (uint32_t)(ic & 1) * GST_B;
        if (ic + 1 < NC) {
            load_tile2(base + (uint32_t)((ic + 1) & 1) * GST_B, Ah, Bh, m0, n0, K, ic + 1, t);
            cp_commit();
            cp_wait1();
        } else {
            cp_wait0();
        }
        __syncthreads();

        uint32_t Ahb = cb, Bhb = cb + GA_B;
#pragma unroll
        for (int kp2 = 0; kp2 < 2; kp2++) {
            uint32_t ah[4][2][4];
#pragma unroll
            for (int mt = 0; mt < 4; mt++)
#pragma unroll
                for (int ks = 0; ks < 2; ks++) {
                    int row = warp_m + mt * 16 + (lane & 15);
                    int ch  = kp2 * 4 + ks * 2 + (lane >> 4);
                    ldsm4(ah[mt][ks], sw(Ahb, row, ch));
                }
#pragma unroll
            for (int np = 0; np < 4; np++) {
                uint32_t bh[2][4];
#pragma unroll
                for (int j = 0; j < 2; j++) {
                    int row = warp_n + (np * 2 + j) * 8 + (lane & 7);
                    int ch  = kp2 * 4 + ((lane >> 3) & 3);
                    ldsm4(bh[j], sw(Bhb, row, ch));
                }
#pragma unroll
                for (int ks = 0; ks < 2; ks++)
#pragma unroll
                    for (int mt = 0; mt < 4; mt++)
#pragma unroll
                        for (int j = 0; j < 2; j++)
                            mma_f16(acc[mt][np * 2 + j], ah[mt][ks], &bh[j][ks * 2]);
            }
        }
        __syncthreads();
    }

    int rbase = m0 + warp_m + (lane >> 2);
    int cbase = n0 + warp_n + (lane & 3) * 2;
#pragma unroll
    for (int mt = 0; mt < 4; mt++)
#pragma unroll
        for (int nt = 0; nt < 8; nt++)
#pragma unroll
            for (int hh = 0; hh < 2; hh++) {
                int row = rbase + mt * 16 + hh * 8;
                int col = cbase + nt * 8;
                float v0 = acc[mt][nt][hh * 2 + 0] + bias[col];
                float v1 = acc[mt][nt][hh * 2 + 1] + bias[col + 1];
                size_t off = (size_t)row * N + col;
                if (MODE == 1) {
                    v0 = 0.5f * v0 * (1.0f + erff(v0 * 0.70710678118654752f));
                    v1 = 0.5f * v1 * (1.0f + erff(v1 * 0.70710678118654752f));
                    ((uint32_t*)outp)[off >> 1] = f16x2(v1, v0);
                } else {
                    const float2 rr = *(const float2*)(resid + off);
                    float2 ov = { v0 + rr.x, v1 + rr.y };
                    *(float2*)((float*)outp + off) = ov;
                }
            }
}

// ---------------- launch ----------------
extern "C" void kernel_launch(void* const* d_in, const int* in_sizes, int n_in,
                              void* d_out, int out_size)
{
    const float* x    = (const float*)d_in[0];
    const float* ln1g = (const float*)d_in[1];
    const float* ln1b = (const float*)d_in[2];
    const float* Wq   = (const float*)d_in[3];
    const float* bq   = (const float*)d_in[4];
    const float* Wk   = (const float*)d_in[5];
    const float* bk   = (const float*)d_in[6];
    const float* Wv   = (const float*)d_in[7];
    const float* bv   = (const float*)d_in[8];
    const float* ln2g = (const float*)d_in[9];
    const float* ln2b = (const float*)d_in[10];
    const float* W1   = (const float*)d_in[11];
    const float* b1   = (const float*)d_in[12];
    const float* W2   = (const float*)d_in[13];
    const float* b2   = (const float*)d_in[14];
    float* out = (float*)d_out;

    float* x1;
    __half *lnx, *lnh, *qf, *kf, *vt, *acth, *w1h, *w2h, *wqkv;
    cudaGetSymbolAddress((void**)&lnx,  g_lnx);
    cudaGetSymbolAddress((void**)&lnh,  g_lnh);
    cudaGetSymbolAddress((void**)&qf,   g_qf);
    cudaGetSymbolAddress((void**)&kf,   g_kf);
    cudaGetSymbolAddress((void**)&vt,   g_vt);
    cudaGetSymbolAddress((void**)&x1,   g_x1);
    cudaGetSymbolAddress((void**)&acth, g_acth);
    cudaGetSymbolAddress((void**)&w1h,  g_w1h);
    cudaGetSymbolAddress((void**)&w2h,  g_w2h);
    cudaGetSymbolAddress((void**)&wqkv, g_wqkv);

    const int ATTN_SMEM = 16384 + 3 * AT_BUF;   // 65536 (2 CTAs/SM => 128KB)
    cudaFuncSetAttribute((const void*)attn_mma_kernel,
                         cudaFuncAttributeMaxDynamicSharedMemorySize, ATTN_SMEM);
    const int GEMM_SMEM = 2 * GST_B + 256;      // 98560
    cudaFuncSetAttribute(gemm_hmma_kernel<1>,
                         cudaFuncAttributeMaxDynamicSharedMemorySize, GEMM_SMEM);
    cudaFuncSetAttribute(gemm_hmma_kernel<2>,
                         cudaFuncAttributeMaxDynamicSharedMemorySize, GEMM_SMEM);
    cudaFuncSetAttribute((const void*)qkv_mma_kernel,
                         cudaFuncAttributeMaxDynamicSharedMemorySize, QKV_SMEM);

    convert_w12_kernel<<<(DMLP * DMODEL + 255) / 256, 256>>>(W1, w1h, W2, w2h);
    convert_wqkv_kernel<<<(NHEAD * HDIM * HDIM + 255) / 256, 256>>>(Wq, Wk, Wv, wqkv);

    // 1) LN1 -> f16
    ln_f16_kernel<<<TOKENS, 256>>>(x, ln1g, ln1b, lnx);
    // 2) HMMA QKV
    qkv_mma_kernel<<<dim3(TOKENS / 128, NHEAD), 256, QKV_SMEM>>>(
        lnx, wqkv, bq, bk, bv, qf, kf, vt);
    // 3) HMMA attention + residual -> x1 (3-stage, single sync, 2 CTAs/SM)
    attn_mma_kernel<<<dim3(SEQ / 128, NHEAD, BATCH), 256, ATTN_SMEM>>>(qf, kf, vt, x, x1);
    // 4) LN2 -> f16
    ln_f16_kernel<<<TOKENS, 256>>>(x1, ln2g, ln2b, lnh);
    // 5) MLP up + GELU -> act f16
    gemm_hmma_kernel<1><<<dim3(DMLP / 128, TOKENS / 256), 256, GEMM_SMEM>>>(
        lnh, w1h, b1, nullptr, (void*)acth, DMLP, DMODEL);
    // 6) MLP down + bias + residual -> out
    gemm_hmma_kernel<2><<<dim3(DMODEL / 128, TOKENS / 256), 256, GEMM_SMEM>>>(
        acth, w2h, b2, x1, (void*)out, DMODEL, DMLP);
}

// round 15
// speedup vs baseline: 1.0831x; 1.0319x over previous
#include <cuda_runtime.h>
#include <cuda_bf16.h>
#include <cuda_fp16.h>
#include <math.h>
#include <stdint.h>

#define TOKENS 16384
#define DMODEL 768
#define NHEAD  12
#define HDIM   64
#define DMLP   3072
#define SEQ    1024
#define BATCH  16

// ---------------- scratch (device globals; no cudaMalloc allowed) ----------------
__device__ __half g_lnx [TOKENS * DMODEL];   // LN1 out f16 (qkv input)
__device__ __half g_lnh [TOKENS * DMODEL];   // LN2 out f16
__device__ __half g_qf  [TOKENS * DMODEL];   // q f16, pre-scaled by 0.125 [tok][h*64+d]
__device__ __half g_kf  [TOKENS * DMODEL];   // k f16
__device__ __half g_vt  [TOKENS * DMODEL];   // V^T f16: [(b*12+h)*64+d][1024]
__device__ float  g_x1  [TOKENS * DMODEL];   // x + attn
__device__ __half g_acth[TOKENS * DMLP];     // GELU out f16
__device__ __half g_w1h [DMLP * DMODEL];     // W1 f16
__device__ __half g_w2h [DMODEL * DMLP];     // W2 f16
__device__ __half g_wqkv[3 * NHEAD * HDIM * HDIM];  // Wq|Wk|Wv f16

// ---------------- PTX helpers (portable sm_80-class only) ----------------
__device__ __forceinline__ void cp16(uint32_t s, const void* g) {
    asm volatile("cp.async.cg.shared.global [%0], [%1], 16;" :: "r"(s), "l"(g));
}
__device__ __forceinline__ void cp_commit() { asm volatile("cp.async.commit_group;" ::: "memory"); }
__device__ __forceinline__ void cp_wait1()  { asm volatile("cp.async.wait_group 1;" ::: "memory"); }
__device__ __forceinline__ void cp_wait0()  { asm volatile("cp.async.wait_group 0;" ::: "memory"); }

__device__ __forceinline__ void ldsm4(uint32_t* r, uint32_t addr) {
    asm volatile("ldmatrix.sync.aligned.m8n8.x4.shared.b16 {%0,%1,%2,%3}, [%4];"
                 : "=r"(r[0]), "=r"(r[1]), "=r"(r[2]), "=r"(r[3]) : "r"(addr));
}
__device__ __forceinline__ void mma_f16(float* d, const uint32_t* a, const uint32_t* b) {
    asm("mma.sync.aligned.m16n8k16.row.col.f32.f16.f16.f32 "
        "{%0,%1,%2,%3}, {%4,%5,%6,%7}, {%8,%9}, {%0,%1,%2,%3};"
        : "+f"(d[0]), "+f"(d[1]), "+f"(d[2]), "+f"(d[3])
        : "r"(a[0]), "r"(a[1]), "r"(a[2]), "r"(a[3]), "r"(b[0]), "r"(b[1]));
}
__device__ __forceinline__ uint32_t f16x2(float hi, float lo) {
    uint32_t u;
    asm("cvt.rn.f16x2.f32 %0, %1, %2;" : "=r"(u) : "f"(hi), "f"(lo));
    return u;
}

// ---------------- LayerNorm: warp-per-token, no smem, no block sync ----------------
__global__ void __launch_bounds__(256) ln_f16_kernel(
    const float* __restrict__ x, const float* __restrict__ g,
    const float* __restrict__ b, __half* __restrict__ oh)
{
    int warp = threadIdx.x >> 5, lane = threadIdx.x & 31;
    size_t tok = (size_t)blockIdx.x * 8 + warp;
    const float4* xr = (const float4*)(x + tok * DMODEL);

    float4 v[6];
    float s = 0.f;
#pragma unroll
    for (int i = 0; i < 6; i++) {
        v[i] = xr[lane + 32 * i];
        s += v[i].x + v[i].y + v[i].z + v[i].w;
    }
#pragma unroll
    for (int o = 16; o > 0; o >>= 1) s += __shfl_xor_sync(0xffffffffu, s, o);
    float mu = s * (1.0f / DMODEL);

    float sq = 0.f;
#pragma unroll
    for (int i = 0; i < 6; i++) {
        float d0 = v[i].x - mu, d1 = v[i].y - mu, d2 = v[i].z - mu, d3 = v[i].w - mu;
        sq += d0 * d0 + d1 * d1 + d2 * d2 + d3 * d3;
    }
#pragma unroll
    for (int o = 16; o > 0; o >>= 1) sq += __shfl_xor_sync(0xffffffffu, sq, o);
    float rs = rsqrtf(sq * (1.0f / DMODEL) + 1e-5f);

    uint2* orow = (uint2*)(oh + tok * DMODEL);
#pragma unroll
    for (int i = 0; i < 6; i++) {
        int idx = lane + 32 * i;
        float4 g4 = ((const float4*)g)[idx];
        float4 b4 = ((const float4*)b)[idx];
        uint2 pk;
        pk.x = f16x2((v[i].y - mu) * rs * g4.y + b4.y, (v[i].x - mu) * rs * g4.x + b4.x);
        pk.y = f16x2((v[i].w - mu) * rs * g4.w + b4.w, (v[i].z - mu) * rs * g4.z + b4.z);
        orow[idx] = pk;
    }
}

// ---------------- weight conversions (W1+W2 merged) ----------------
__global__ void convert_w12_kernel(const float* __restrict__ W1, __half* __restrict__ w1h,
                                   const float* __restrict__ W2, __half* __restrict__ w2h)
{
    int i = blockIdx.x * 256 + threadIdx.x;
    const int n = DMLP * DMODEL;
    if (i < n) {
        w1h[i] = __float2half(W1[i]);
        w2h[i] = __float2half(W2[i]);
    }
}
__global__ void convert_wqkv_kernel(const float* __restrict__ Wq, const float* __restrict__ Wk,
                                    const float* __restrict__ Wv, __half* __restrict__ o)
{
    int i = blockIdx.x * 256 + threadIdx.x;
    const int n = NHEAD * HDIM * HDIM;
    if (i < n) {
        o[i]         = __float2half(Wq[i]);
        o[n + i]     = __float2half(Wk[i]);
        o[2 * n + i] = __float2half(Wv[i]);
    }
}

// ---------------- shared swizzle: 128B rows, 8 x 16B chunks ----------------
__device__ __forceinline__ uint32_t sw(uint32_t b, int row, int ch) {
    return b + (uint32_t)(row * 128) + (uint32_t)((ch ^ (row & 7)) << 4);
}

// ---------------- HMMA QKV: per-CTA 128 tokens x one head, 2 CTAs/SM ----------------
#define QX_OFF  0
#define QW_OFF  16384
#define QV_OFF  (16384 + 3 * 8192)
#define QKV_SMEM (QV_OFF + 64 * 272)

__global__ void __launch_bounds__(256, 2) qkv_mma_kernel(
    const __half* __restrict__ lnx, const __half* __restrict__ wqkv,
    const float* __restrict__ bq, const float* __restrict__ bk, const float* __restrict__ bv,
    __half* __restrict__ qf, __half* __restrict__ kf, __half* __restrict__ vt)
{
    extern __shared__ char dsm[];
    uint32_t sb = (uint32_t)__cvta_generic_to_shared(dsm);
    const int hh = blockIdx.y;
    const int t0 = blockIdx.x * 128;
    const int t = threadIdx.x, lane = t & 31, w = t >> 5;
    const int ho = hh * HDIM;
    const int bh = (t0 >> 10) * 12 + hh;

#pragma unroll
    for (int i = 0; i < 4; i++) {
        int idx = t + 256 * i;
        int r = idx >> 3, c = idx & 7;
        cp16(sw(sb + QX_OFF, r, c), lnx + (size_t)(t0 + r) * DMODEL + ho + c * 8);
    }
#pragma unroll
    for (int m = 0; m < 3; m++)
#pragma unroll
        for (int i = 0; i < 2; i++) {
            int idx = t + 256 * i;
            int r = idx >> 3, c = idx & 7;
            cp16(sw(sb + QW_OFF + m * 8192, r, c),
                 wqkv + (size_t)(m * NHEAD + hh) * 4096 + r * 64 + c * 8);
        }
    cp_commit();
    cp_wait0();
    __syncthreads();

    uint32_t af[4][4];
#pragma unroll
    for (int ks = 0; ks < 4; ks++) {
        int r = w * 16 + (lane & 15);
        int c = ks * 2 + (lane >> 4);
        ldsm4(af[ks], sw(sb + QX_OFF, r, c));
    }

    const float* biases[3] = { bq + ho, bk + ho, bv + ho };

#pragma unroll
    for (int m = 0; m < 3; m++) {
        float acc[8][4] = {};
        uint32_t wb0 = sb + QW_OFF + m * 8192;
#pragma unroll
        for (int kp = 0; kp < 2; kp++) {
            uint32_t bf[8][4];
#pragma unroll
            for (int j = 0; j < 8; j++) {
                int r = j * 8 + (lane & 7);
                int c = kp * 4 + ((lane >> 3) & 3);
                ldsm4(bf[j], sw(wb0, r, c));
            }
#pragma unroll
            for (int s = 0; s < 2; s++)
#pragma unroll
                for (int j = 0; j < 8; j++)
                    mma_f16(acc[j], af[kp * 2 + s], &bf[j][s * 2]);
        }
        const float* bias = biases[m];
        int r0 = w * 16 + (lane >> 2);
        int cb = 2 * (lane & 3);
        if (m < 2) {
            __half* dst = (m == 0) ? qf : kf;
            float scale = (m == 0) ? 0.125f : 1.0f;
#pragma unroll
            for (int j = 0; j < 8; j++)
#pragma unroll
                for (int h2 = 0; h2 < 2; h2++) {
                    int col = cb + j * 8;
                    int row = t0 + r0 + h2 * 8;
                    float v0 = (acc[j][h2 * 2 + 0] + bias[col])     * scale;
                    float v1 = (acc[j][h2 * 2 + 1] + bias[col + 1]) * scale;
                    *(uint32_t*)(dst + (size_t)row * DMODEL + ho + col) = f16x2(v1, v0);
                }
        } else {
#pragma unroll
            for (int j = 0; j < 8; j++)
#pragma unroll
                for (int h2 = 0; h2 < 2; h2++) {
                    int col = cb + j * 8;
                    int rl  = r0 + h2 * 8;
                    float v0 = acc[j][h2 * 2 + 0] + bias[col];
                    float v1 = acc[j][h2 * 2 + 1] + bias[col + 1];
                    *(__half*)(dsm + QV_OFF + col * 272 + rl * 2)       = __float2half(v0);
                    *(__half*)(dsm + QV_OFF + (col + 1) * 272 + rl * 2) = __float2half(v1);
                }
        }
    }
    __syncthreads();
    int pos0 = t0 & 1023;
#pragma unroll
    for (int i = 0; i < 4; i++) {
        int idx = t + 256 * i;
        int o = idx >> 4, q16 = idx & 15;
        uint4 val = *(const uint4*)(dsm + QV_OFF + o * 272 + q16 * 16);
        *(uint4*)(vt + ((size_t)(bh * 64 + o)) * 1024 + pos0 + q16 * 8) = val;
    }
}

// ---------------- HMMA flash attention: 256 threads, 3-stage, single sync, 2 CTAs/SM ----------------
#define AT_BUF 16384

__global__ void __launch_bounds__(256, 2) attn_mma_kernel(
    const __half* __restrict__ qf, const __half* __restrict__ kf,
    const __half* __restrict__ vt,
    const float* __restrict__ x, float* __restrict__ out)
{
    extern __shared__ char dsm[];
    uint32_t sb = (uint32_t)__cvta_generic_to_shared(dsm);

    const int b = blockIdx.z, hh = blockIdx.y;
    const int q0 = blockIdx.x * 128;
    const int t = threadIdx.x, lane = t & 31, w = t >> 5;
    const int wq = w * 16;
    const int bh = b * 12 + hh;
    const int ho = hh * HDIM;
    const size_t tok0 = (size_t)b * 1024 + q0;
    const int kg0 = b * 1024;

    const uint32_t Qb = sb;
    const uint32_t Bb = sb + 16384;

#pragma unroll
    for (int i = 0; i < 4; i++) {
        int idx = t + 256 * i;
        int r = idx >> 3, c = idx & 7;
        cp16(sw(Qb, r, c), qf + (tok0 + r) * DMODEL + ho + c * 8);
    }
#pragma unroll
    for (int i = 0; i < 2; i++) {
        int idx = t + 256 * i;
        int r = idx >> 3, c = idx & 7;
        cp16(sw(Bb, r, c),        kf + (size_t)(kg0 + r) * DMODEL + ho + c * 8);
        cp16(sw(Bb + 8192, r, c), vt + ((size_t)(bh * 64 + r)) * 1024 + c * 8);
    }
    cp_commit();
#pragma unroll
    for (int i = 0; i < 2; i++) {
        int idx = t + 256 * i;
        int r = idx >> 3, c = idx & 7;
        cp16(sw(Bb + AT_BUF, r, c),        kf + (size_t)(kg0 + 64 + r) * DMODEL + ho + c * 8);
        cp16(sw(Bb + AT_BUF + 8192, r, c), vt + ((size_t)(bh * 64 + r)) * 1024 + 64 + c * 8);
    }
    cp_commit();

    float oacc[8][4] = {};
    float rs0 = 0.f, rs1 = 0.f;
    uint32_t af[4][4];

    for (int kt = 0; kt < 16; kt++) {
        if (kt < 15) cp_wait1(); else cp_wait0();
        __syncthreads();

        if (kt + 2 < 16) {
            uint32_t nb = Bb + (uint32_t)((kt + 2) % 3) * AT_BUF;
            int kg = kg0 + (kt + 2) * 64;
#pragma unroll
            for (int i = 0; i < 2; i++) {
                int idx = t + 256 * i;
                int r = idx >> 3, c = idx & 7;
                cp16(sw(nb, r, c),        kf + (size_t)(kg + r) * DMODEL + ho + c * 8);
                cp16(sw(nb + 8192, r, c), vt + ((size_t)(bh * 64 + r)) * 1024 + (kt + 2) * 64 + c * 8);
            }
            cp_commit();
        }

        uint32_t cb = Bb + (uint32_t)(kt % 3) * AT_BUF;

        if (kt == 0) {
#pragma unroll
            for (int ks = 0; ks < 4; ks++) {
                int r = wq + (lane & 15);
                int c = ks * 2 + (lane >> 4);
                ldsm4(af[ks], sw(Qb, r, c));
            }
        }

        float sacc[8][4] = {};
#pragma unroll
        for (int kp = 0; kp < 2; kp++) {
            uint32_t bf[8][4];
#pragma unroll
            for (int j = 0; j < 8; j++) {
                int r = j * 8 + (lane & 7);
                int c = kp * 4 + ((lane >> 3) & 3);
                ldsm4(bf[j], sw(cb, r, c));
            }
#pragma unroll
            for (int s = 0; s < 2; s++)
#pragma unroll
                for (int j = 0; j < 8; j++)
                    mma_f16(sacc[j], af[kp * 2 + s], &bf[j][s * 2]);
        }

        uint32_t pa[4][4];
#pragma unroll
        for (int j = 0; j < 8; j++) {
            float e0 = __expf(sacc[j][0]);
            float e1 = __expf(sacc[j][1]);
            float e2 = __expf(sacc[j][2]);
            float e3 = __expf(sacc[j][3]);
            rs0 += e0 + e1;
            rs1 += e2 + e3;
            pa[j >> 1][(j & 1) * 2 + 0] = f16x2(e1, e0);
            pa[j >> 1][(j & 1) * 2 + 1] = f16x2(e3, e2);
        }

        uint32_t vb0 = cb + 8192;
#pragma unroll
        for (int kp = 0; kp < 2; kp++) {
            uint32_t vb[8][4];
#pragma unroll
            for (int j = 0; j < 8; j++) {
                int r = j * 8 + (lane & 7);
                int c = kp * 4 + ((lane >> 3) & 3);
                ldsm4(vb[j], sw(vb0, r, c));
            }
#pragma unroll
            for (int s = 0; s < 2; s++)
#pragma unroll
                for (int j = 0; j < 8; j++)
                    mma_f16(oacc[j], pa[kp * 2 + s], &vb[j][s * 2]);
        }
    }

    rs0 += __shfl_xor_sync(0xffffffffu, rs0, 1);
    rs0 += __shfl_xor_sync(0xffffffffu, rs0, 2);
    rs1 += __shfl_xor_sync(0xffffffffu, rs1, 1);
    rs1 += __shfl_xor_sync(0xffffffffu, rs1, 2);
    float inv0 = 1.0f / rs0, inv1 = 1.0f / rs1;

    size_t row0 = tok0 + wq + (lane >> 2);
    size_t row1 = row0 + 8;
#pragma unroll
    for (int j = 0; j < 8; j++) {
        int col = ho + j * 8 + 2 * (lane & 3);
        size_t o0 = row0 * DMODEL + col;
        size_t o1 = row1 * DMODEL + col;
        float2 x0 = *(const float2*)(x + o0);
        float2 x1v = *(const float2*)(x + o1);
        float2 r0 = { oacc[j][0] * inv0 + x0.x,  oacc[j][1] * inv0 + x0.y };
        float2 r1 = { oacc[j][2] * inv1 + x1v.x, oacc[j][3] * inv1 + x1v.y };
        *(float2*)(out + o0) = r0;
        *(float2*)(out + o1) = r1;
    }
}

// ---------------- HMMA plain-f16 GEMM: 256x128 CTA tile, 64x64 warp tile (proven) ----------------
#define GA_B   32768
#define GB_B   16384
#define GST_B  (GA_B + GB_B)

__device__ __forceinline__ void load_tile2(uint32_t sb,
    const __half* __restrict__ Ah, const __half* __restrict__ Bh,
    int m0, int n0, int K, int ic, int t)
{
#pragma unroll
    for (int i = 0; i < 8; i++) {
        int idx = t + 256 * i;
        int row = idx >> 3, ch = idx & 7;
        cp16(sw(sb, row, ch), Ah + (size_t)(m0 + row) * K + ic * 64 + ch * 8);
    }
#pragma unroll
    for (int i = 0; i < 4; i++) {
        int idx = t + 256 * i;
        int row = idx >> 3, ch = idx & 7;
        cp16(sw(sb + GA_B, row, ch), Bh + (size_t)(n0 + row) * K + ic * 64 + ch * 8);
    }
}

template<int MODE>
__global__ void __launch_bounds__(256, 1)
gemm_hmma_kernel(const __half* __restrict__ Ah, const __half* __restrict__ Bh,
                 const float* __restrict__ bias, const float* __restrict__ resid,
                 void* __restrict__ outp, int N, int K)
{
    extern __shared__ char dsm[];
    uint32_t smem_u32 = (uint32_t)__cvta_generic_to_shared(dsm);
    uint32_t base = (smem_u32 + 127) & ~127u;

    const int t = threadIdx.x;
    const int lane = t & 31, wid = t >> 5;
    const int m0 = blockIdx.y * 256, n0 = blockIdx.x * 128;
    const int warp_m = (wid >> 1) * 64, warp_n = (wid & 1) * 64;

    float acc[4][8][4] = {};
    const int NC = K >> 6;

    load_tile2(base, Ah, Bh, m0, n0, K, 0, t);
    cp_commit();

    for (int ic = 0; ic < NC; ic++) {
        uint32_t cb = base + (uint32_t)(ic & 1) * GST_B;
        if (ic + 1 < NC) {
            load_tile2(base + (uint32_t)((ic + 1) & 1) * GST_B, Ah, Bh, m0, n0, K, ic + 1, t);
            cp_commit();
            cp_wait1();
        } else {
            cp_wait0();
        }
        __syncthreads();

        uint32_t Ahb = cb, Bhb = cb + GA_B;
#pragma unroll
        for (int kp2 = 0; kp2 < 2; kp2++) {
            uint32_t ah[4][2][4];
#pragma unroll
            for (int mt = 0; mt < 4; mt++)
#pragma unroll
                for (int ks = 0; ks < 2; ks++) {
                    int row = warp_m + mt * 16 + (lane & 15);
                    int ch  = kp2 * 4 + ks * 2 + (lane >> 4);
                    ldsm4(ah[mt][ks], sw(Ahb, row, ch));
                }
#pragma unroll
            for (int np = 0; np < 4; np++) {
                uint32_t bh[2][4];
#pragma unroll
                for (int j = 0; j < 2; j++) {
                    int row = warp_n + (np * 2 + j) * 8 + (lane & 7);
                    int ch  = kp2 * 4 + ((lane >> 3) & 3);
                    ldsm4(bh[j], sw(Bhb, row, ch));
                }
#pragma unroll
                for (int ks = 0; ks < 2; ks++)
#pragma unroll
                    for (int mt = 0; mt < 4; mt++)
#pragma unroll
                        for (int j = 0; j < 2; j++)
                            mma_f16(acc[mt][np * 2 + j], ah[mt][ks], &bh[j][ks * 2]);
            }
        }
        __syncthreads();
    }

    int rbase = m0 + warp_m + (lane >> 2);
    int cbase = n0 + warp_n + (lane & 3) * 2;
#pragma unroll
    for (int mt = 0; mt < 4; mt++)
#pragma unroll
        for (int nt = 0; nt < 8; nt++)
#pragma unroll
            for (int hh = 0; hh < 2; hh++) {
                int row = rbase + mt * 16 + hh * 8;
                int col = cbase + nt * 8;
                float v0 = acc[mt][nt][hh * 2 + 0] + bias[col];
                float v1 = acc[mt][nt][hh * 2 + 1] + bias[col + 1];
                size_t off = (size_t)row * N + col;
                if (MODE == 1) {
                    v0 = 0.5f * v0 * (1.0f + erff(v0 * 0.70710678118654752f));
                    v1 = 0.5f * v1 * (1.0f + erff(v1 * 0.70710678118654752f));
                    ((uint32_t*)outp)[off >> 1] = f16x2(v1, v0);
                } else {
                    const float2 rr = *(const float2*)(resid + off);
                    float2 ov = { v0 + rr.x, v1 + rr.y };
                    *(float2*)((float*)outp + off) = ov;
                }
            }
}

// ---------------- launch ----------------
extern "C" void kernel_launch(void* const* d_in, const int* in_sizes, int n_in,
                              void* d_out, int out_size)
{
    const float* x    = (const float*)d_in[0];
    const float* ln1g = (const float*)d_in[1];
    const float* ln1b = (const float*)d_in[2];
    const float* Wq   = (const float*)d_in[3];
    const float* bq   = (const float*)d_in[4];
    const float* Wk   = (const float*)d_in[5];
    const float* bk   = (const float*)d_in[6];
    const float* Wv   = (const float*)d_in[7];
    const float* bv   = (const float*)d_in[8];
    const float* ln2g = (const float*)d_in[9];
    const float* ln2b = (const float*)d_in[10];
    const float* W1   = (const float*)d_in[11];
    const float* b1   = (const float*)d_in[12];
    const float* W2   = (const float*)d_in[13];
    const float* b2   = (const float*)d_in[14];
    float* out = (float*)d_out;

    float* x1;
    __half *lnx, *lnh, *qf, *kf, *vt, *acth, *w1h, *w2h, *wqkv;
    cudaGetSymbolAddress((void**)&lnx,  g_lnx);
    cudaGetSymbolAddress((void**)&lnh,  g_lnh);
    cudaGetSymbolAddress((void**)&qf,   g_qf);
    cudaGetSymbolAddress((void**)&kf,   g_kf);
    cudaGetSymbolAddress((void**)&vt,   g_vt);
    cudaGetSymbolAddress((void**)&x1,   g_x1);
    cudaGetSymbolAddress((void**)&acth, g_acth);
    cudaGetSymbolAddress((void**)&w1h,  g_w1h);
    cudaGetSymbolAddress((void**)&w2h,  g_w2h);
    cudaGetSymbolAddress((void**)&wqkv, g_wqkv);

    const int ATTN_SMEM = 16384 + 3 * AT_BUF;   // 65536 (2 CTAs/SM)
    cudaFuncSetAttribute((const void*)attn_mma_kernel,
                         cudaFuncAttributeMaxDynamicSharedMemorySize, ATTN_SMEM);
    const int GEMM_SMEM = 2 * GST_B + 256;      // 98560
    cudaFuncSetAttribute(gemm_hmma_kernel<1>,
                         cudaFuncAttributeMaxDynamicSharedMemorySize, GEMM_SMEM);
    cudaFuncSetAttribute(gemm_hmma_kernel<2>,
                         cudaFuncAttributeMaxDynamicSharedMemorySize, GEMM_SMEM);
    cudaFuncSetAttribute((const void*)qkv_mma_kernel,
                         cudaFuncAttributeMaxDynamicSharedMemorySize, QKV_SMEM);

    convert_w12_kernel<<<(DMLP * DMODEL + 255) / 256, 256>>>(W1, w1h, W2, w2h);
    convert_wqkv_kernel<<<(NHEAD * HDIM * HDIM + 255) / 256, 256>>>(Wq, Wk, Wv, wqkv);

    // 1) LN1 -> f16 (warp-per-token)
    ln_f16_kernel<<<TOKENS / 8, 256>>>(x, ln1g, ln1b, lnx);
    // 2) HMMA QKV (2 CTAs/SM)
    qkv_mma_kernel<<<dim3(TOKENS / 128, NHEAD), 256, QKV_SMEM>>>(
        lnx, wqkv, bq, bk, bv, qf, kf, vt);
    // 3) HMMA attention + residual -> x1
    attn_mma_kernel<<<dim3(SEQ / 128, NHEAD, BATCH), 256, ATTN_SMEM>>>(qf, kf, vt, x, x1);
    // 4) LN2 -> f16
    ln_f16_kernel<<<TOKENS / 8, 256>>>(x1, ln2g, ln2b, lnh);
    // 5) MLP up + GELU -> act f16
    gemm_hmma_kernel<1><<<dim3(DMLP / 128, TOKENS / 256), 256, GEMM_SMEM>>>(
        lnh, w1h, b1, nullptr, (void*)acth, DMLP, DMODEL);
    // 6) MLP down + bias + residual -> out
    gemm_hmma_kernel<2><<<dim3(DMODEL / 128, TOKENS / 256), 256, GEMM_SMEM>>>(
        acth, w2h, b2, x1, (void*)out, DMODEL, DMLP);
}

// round 16
// speedup vs baseline: 1.0857x; 1.0024x over previous
#include <cuda_runtime.h>
#include <cuda_bf16.h>
#include <cuda_fp16.h>
#include <math.h>
#include <stdint.h>

#define TOKENS 16384
#define DMODEL 768
#define NHEAD  12
#define HDIM   64
#define DMLP   3072
#define SEQ    1024
#define BATCH  16

// ---------------- scratch (device globals; no cudaMalloc allowed) ----------------
__device__ __half g_lnx [TOKENS * DMODEL];   // LN1 out f16 (qkv input)
__device__ __half g_lnh [TOKENS * DMODEL];   // LN2 out f16
__device__ __half g_qf  [TOKENS * DMODEL];   // q f16, pre-scaled by 0.125 [tok][h*64+d]
__device__ __half g_kf  [TOKENS * DMODEL];   // k f16
__device__ __half g_vt  [TOKENS * DMODEL];   // V^T f16: [(b*12+h)*64+d][1024]
__device__ float  g_x1  [TOKENS * DMODEL];   // x + attn
__device__ __half g_acth[TOKENS * DMLP];     // GELU out f16
__device__ __half g_w1h [DMLP * DMODEL];     // W1 f16
__device__ __half g_w2h [DMODEL * DMLP];     // W2 f16
__device__ __half g_wqkv[3 * NHEAD * HDIM * HDIM];  // Wq|Wk|Wv f16

// ---------------- PTX helpers (portable sm_80-class only) ----------------
__device__ __forceinline__ void cp16(uint32_t s, const void* g) {
    asm volatile("cp.async.cg.shared.global [%0], [%1], 16;" :: "r"(s), "l"(g));
}
__device__ __forceinline__ void cp_commit() { asm volatile("cp.async.commit_group;" ::: "memory"); }
__device__ __forceinline__ void cp_wait1()  { asm volatile("cp.async.wait_group 1;" ::: "memory"); }
__device__ __forceinline__ void cp_wait0()  { asm volatile("cp.async.wait_group 0;" ::: "memory"); }

__device__ __forceinline__ void ldsm4(uint32_t* r, uint32_t addr) {
    asm volatile("ldmatrix.sync.aligned.m8n8.x4.shared.b16 {%0,%1,%2,%3}, [%4];"
                 : "=r"(r[0]), "=r"(r[1]), "=r"(r[2]), "=r"(r[3]) : "r"(addr));
}
__device__ __forceinline__ void mma_f16(float* d, const uint32_t* a, const uint32_t* b) {
    asm("mma.sync.aligned.m16n8k16.row.col.f32.f16.f16.f32 "
        "{%0,%1,%2,%3}, {%4,%5,%6,%7}, {%8,%9}, {%0,%1,%2,%3};"
        : "+f"(d[0]), "+f"(d[1]), "+f"(d[2]), "+f"(d[3])
        : "r"(a[0]), "r"(a[1]), "r"(a[2]), "r"(a[3]), "r"(b[0]), "r"(b[1]));
}
__device__ __forceinline__ uint32_t f16x2(float hi, float lo) {
    uint32_t u;
    asm("cvt.rn.f16x2.f32 %0, %1, %2;" : "=r"(u) : "f"(hi), "f"(lo));
    return u;
}

// ---------------- LayerNorm: warp-per-token, no smem, no block sync ----------------
__global__ void __launch_bounds__(256) ln_f16_kernel(
    const float* __restrict__ x, const float* __restrict__ g,
    const float* __restrict__ b, __half* __restrict__ oh)
{
    int warp = threadIdx.x >> 5, lane = threadIdx.x & 31;
    size_t tok = (size_t)blockIdx.x * 8 + warp;
    const float4* xr = (const float4*)(x + tok * DMODEL);

    float4 v[6];
    float s = 0.f;
#pragma unroll
    for (int i = 0; i < 6; i++) {
        v[i] = xr[lane + 32 * i];
        s += v[i].x + v[i].y + v[i].z + v[i].w;
    }
#pragma unroll
    for (int o = 16; o > 0; o >>= 1) s += __shfl_xor_sync(0xffffffffu, s, o);
    float mu = s * (1.0f / DMODEL);

    float sq = 0.f;
#pragma unroll
    for (int i = 0; i < 6; i++) {
        float d0 = v[i].x - mu, d1 = v[i].y - mu, d2 = v[i].z - mu, d3 = v[i].w - mu;
        sq += d0 * d0 + d1 * d1 + d2 * d2 + d3 * d3;
    }
#pragma unroll
    for (int o = 16; o > 0; o >>= 1) sq += __shfl_xor_sync(0xffffffffu, sq, o);
    float rs = rsqrtf(sq * (1.0f / DMODEL) + 1e-5f);

    uint2* orow = (uint2*)(oh + tok * DMODEL);
#pragma unroll
    for (int i = 0; i < 6; i++) {
        int idx = lane + 32 * i;
        float4 g4 = ((const float4*)g)[idx];
        float4 b4 = ((const float4*)b)[idx];
        uint2 pk;
        pk.x = f16x2((v[i].y - mu) * rs * g4.y + b4.y, (v[i].x - mu) * rs * g4.x + b4.x);
        pk.y = f16x2((v[i].w - mu) * rs * g4.w + b4.w, (v[i].z - mu) * rs * g4.z + b4.z);
        orow[idx] = pk;
    }
}

// ---------------- weight conversions (W1+W2 merged) ----------------
__global__ void convert_w12_kernel(const float* __restrict__ W1, __half* __restrict__ w1h,
                                   const float* __restrict__ W2, __half* __restrict__ w2h)
{
    int i = blockIdx.x * 256 + threadIdx.x;
    const int n = DMLP * DMODEL;
    if (i < n) {
        w1h[i] = __float2half(W1[i]);
        w2h[i] = __float2half(W2[i]);
    }
}
__global__ void convert_wqkv_kernel(const float* __restrict__ Wq, const float* __restrict__ Wk,
                                    const float* __restrict__ Wv, __half* __restrict__ o)
{
    int i = blockIdx.x * 256 + threadIdx.x;
    const int n = NHEAD * HDIM * HDIM;
    if (i < n) {
        o[i]         = __float2half(Wq[i]);
        o[n + i]     = __float2half(Wk[i]);
        o[2 * n + i] = __float2half(Wv[i]);
    }
}

// ---------------- shared swizzle: 128B rows, 8 x 16B chunks ----------------
__device__ __forceinline__ uint32_t sw(uint32_t b, int row, int ch) {
    return b + (uint32_t)(row * 128) + (uint32_t)((ch ^ (row & 7)) << 4);
}

// ---------------- HMMA QKV: per-CTA 128 tokens x one head, 2 CTAs/SM ----------------
#define QX_OFF  0
#define QW_OFF  16384
#define QV_OFF  (16384 + 3 * 8192)
#define QKV_SMEM (QV_OFF + 64 * 272)

__global__ void __launch_bounds__(256, 2) qkv_mma_kernel(
    const __half* __restrict__ lnx, const __half* __restrict__ wqkv,
    const float* __restrict__ bq, const float* __restrict__ bk, const float* __restrict__ bv,
    __half* __restrict__ qf, __half* __restrict__ kf, __half* __restrict__ vt)
{
    extern __shared__ char dsm[];
    uint32_t sb = (uint32_t)__cvta_generic_to_shared(dsm);
    const int hh = blockIdx.y;
    const int t0 = blockIdx.x * 128;
    const int t = threadIdx.x, lane = t & 31, w = t >> 5;
    const int ho = hh * HDIM;
    const int bh = (t0 >> 10) * 12 + hh;

#pragma unroll
    for (int i = 0; i < 4; i++) {
        int idx = t + 256 * i;
        int r = idx >> 3, c = idx & 7;
        cp16(sw(sb + QX_OFF, r, c), lnx + (size_t)(t0 + r) * DMODEL + ho + c * 8);
    }
#pragma unroll
    for (int m = 0; m < 3; m++)
#pragma unroll
        for (int i = 0; i < 2; i++) {
            int idx = t + 256 * i;
            int r = idx >> 3, c = idx & 7;
            cp16(sw(sb + QW_OFF + m * 8192, r, c),
                 wqkv + (size_t)(m * NHEAD + hh) * 4096 + r * 64 + c * 8);
        }
    cp_commit();
    cp_wait0();
    __syncthreads();

    uint32_t af[4][4];
#pragma unroll
    for (int ks = 0; ks < 4; ks++) {
        int r = w * 16 + (lane & 15);
        int c = ks * 2 + (lane >> 4);
        ldsm4(af[ks], sw(sb + QX_OFF, r, c));
    }

    const float* biases[3] = { bq + ho, bk + ho, bv + ho };

#pragma unroll
    for (int m = 0; m < 3; m++) {
        float acc[8][4] = {};
        uint32_t wb0 = sb + QW_OFF + m * 8192;
#pragma unroll
        for (int kp = 0; kp < 2; kp++) {
            uint32_t bf[8][4];
#pragma unroll
            for (int j = 0; j < 8; j++) {
                int r = j * 8 + (lane & 7);
                int c = kp * 4 + ((lane >> 3) & 3);
                ldsm4(bf[j], sw(wb0, r, c));
            }
#pragma unroll
            for (int s = 0; s < 2; s++)
#pragma unroll
                for (int j = 0; j < 8; j++)
                    mma_f16(acc[j], af[kp * 2 + s], &bf[j][s * 2]);
        }
        const float* bias = biases[m];
        int r0 = w * 16 + (lane >> 2);
        int cb = 2 * (lane & 3);
        if (m < 2) {
            __half* dst = (m == 0) ? qf : kf;
            float scale = (m == 0) ? 0.125f : 1.0f;
#pragma unroll
            for (int j = 0; j < 8; j++)
#pragma unroll
                for (int h2 = 0; h2 < 2; h2++) {
                    int col = cb + j * 8;
                    int row = t0 + r0 + h2 * 8;
                    float v0 = (acc[j][h2 * 2 + 0] + bias[col])     * scale;
                    float v1 = (acc[j][h2 * 2 + 1] + bias[col + 1]) * scale;
                    *(uint32_t*)(dst + (size_t)row * DMODEL + ho + col) = f16x2(v1, v0);
                }
        } else {
#pragma unroll
            for (int j = 0; j < 8; j++)
#pragma unroll
                for (int h2 = 0; h2 < 2; h2++) {
                    int col = cb + j * 8;
                    int rl  = r0 + h2 * 8;
                    float v0 = acc[j][h2 * 2 + 0] + bias[col];
                    float v1 = acc[j][h2 * 2 + 1] + bias[col + 1];
                    *(__half*)(dsm + QV_OFF + col * 272 + rl * 2)       = __float2half(v0);
                    *(__half*)(dsm + QV_OFF + (col + 1) * 272 + rl * 2) = __float2half(v1);
                }
        }
    }
    __syncthreads();
    int pos0 = t0 & 1023;
#pragma unroll
    for (int i = 0; i < 4; i++) {
        int idx = t + 256 * i;
        int o = idx >> 4, q16 = idx & 15;
        uint4 val = *(const uint4*)(dsm + QV_OFF + o * 272 + q16 * 16);
        *(uint4*)(vt + ((size_t)(bh * 64 + o)) * 1024 + pos0 + q16 * 8) = val;
    }
}

// ---------------- HMMA flash attention: 256 threads, 3-stage, single sync, 2 CTAs/SM ----------------
#define AT_BUF 16384

__global__ void __launch_bounds__(256, 2) attn_mma_kernel(
    const __half* __restrict__ qf, const __half* __restrict__ kf,
    const __half* __restrict__ vt,
    const float* __restrict__ x, float* __restrict__ out)
{
    extern __shared__ char dsm[];
    uint32_t sb = (uint32_t)__cvta_generic_to_shared(dsm);

    const int b = blockIdx.z, hh = blockIdx.y;
    const int q0 = blockIdx.x * 128;
    const int t = threadIdx.x, lane = t & 31, w = t >> 5;
    const int wq = w * 16;
    const int bh = b * 12 + hh;
    const int ho = hh * HDIM;
    const size_t tok0 = (size_t)b * 1024 + q0;
    const int kg0 = b * 1024;

    const uint32_t Qb = sb;
    const uint32_t Bb = sb + 16384;

#pragma unroll
    for (int i = 0; i < 4; i++) {
        int idx = t + 256 * i;
        int r = idx >> 3, c = idx & 7;
        cp16(sw(Qb, r, c), qf + (tok0 + r) * DMODEL + ho + c * 8);
    }
#pragma unroll
    for (int i = 0; i < 2; i++) {
        int idx = t + 256 * i;
        int r = idx >> 3, c = idx & 7;
        cp16(sw(Bb, r, c),        kf + (size_t)(kg0 + r) * DMODEL + ho + c * 8);
        cp16(sw(Bb + 8192, r, c), vt + ((size_t)(bh * 64 + r)) * 1024 + c * 8);
    }
    cp_commit();
#pragma unroll
    for (int i = 0; i < 2; i++) {
        int idx = t + 256 * i;
        int r = idx >> 3, c = idx & 7;
        cp16(sw(Bb + AT_BUF, r, c),        kf + (size_t)(kg0 + 64 + r) * DMODEL + ho + c * 8);
        cp16(sw(Bb + AT_BUF + 8192, r, c), vt + ((size_t)(bh * 64 + r)) * 1024 + 64 + c * 8);
    }
    cp_commit();

    float oacc[8][4] = {};
    float rs0 = 0.f, rs1 = 0.f;
    uint32_t af[4][4];

    for (int kt = 0; kt < 16; kt++) {
        if (kt < 15) cp_wait1(); else cp_wait0();
        __syncthreads();

        if (kt + 2 < 16) {
            uint32_t nb = Bb + (uint32_t)((kt + 2) % 3) * AT_BUF;
            int kg = kg0 + (kt + 2) * 64;
#pragma unroll
            for (int i = 0; i < 2; i++) {
                int idx = t + 256 * i;
                int r = idx >> 3, c = idx & 7;
                cp16(sw(nb, r, c),        kf + (size_t)(kg + r) * DMODEL + ho + c * 8);
                cp16(sw(nb + 8192, r, c), vt + ((size_t)(bh * 64 + r)) * 1024 + (kt + 2) * 64 + c * 8);
            }
            cp_commit();
        }

        uint32_t cb = Bb + (uint32_t)(kt % 3) * AT_BUF;

        if (kt == 0) {
#pragma unroll
            for (int ks = 0; ks < 4; ks++) {
                int r = wq + (lane & 15);
                int c = ks * 2 + (lane >> 4);
                ldsm4(af[ks], sw(Qb, r, c));
            }
        }

        float sacc[8][4] = {};
#pragma unroll
        for (int kp = 0; kp < 2; kp++) {
            uint32_t bf[8][4];
#pragma unroll
            for (int j = 0; j < 8; j++) {
                int r = j * 8 + (lane & 7);
                int c = kp * 4 + ((lane >> 3) & 3);
                ldsm4(bf[j], sw(cb, r, c));
            }
#pragma unroll
            for (int s = 0; s < 2; s++)
#pragma unroll
                for (int j = 0; j < 8; j++)
                    mma_f16(sacc[j], af[kp * 2 + s], &bf[j][s * 2]);
        }

        uint32_t pa[4][4];
#pragma unroll
        for (int j = 0; j < 8; j++) {
            float e0 = __expf(sacc[j][0]);
            float e1 = __expf(sacc[j][1]);
            float e2 = __expf(sacc[j][2]);
            float e3 = __expf(sacc[j][3]);
            rs0 += e0 + e1;
            rs1 += e2 + e3;
            pa[j >> 1][(j & 1) * 2 + 0] = f16x2(e1, e0);
            pa[j >> 1][(j & 1) * 2 + 1] = f16x2(e3, e2);
        }

        uint32_t vb0 = cb + 8192;
#pragma unroll
        for (int kp = 0; kp < 2; kp++) {
            uint32_t vb[8][4];
#pragma unroll
            for (int j = 0; j < 8; j++) {
                int r = j * 8 + (lane & 7);
                int c = kp * 4 + ((lane >> 3) & 3);
                ldsm4(vb[j], sw(vb0, r, c));
            }
#pragma unroll
            for (int s = 0; s < 2; s++)
#pragma unroll
                for (int j = 0; j < 8; j++)
                    mma_f16(oacc[j], pa[kp * 2 + s], &vb[j][s * 2]);
        }
    }

    rs0 += __shfl_xor_sync(0xffffffffu, rs0, 1);
    rs0 += __shfl_xor_sync(0xffffffffu, rs0, 2);
    rs1 += __shfl_xor_sync(0xffffffffu, rs1, 1);
    rs1 += __shfl_xor_sync(0xffffffffu, rs1, 2);
    float inv0 = 1.0f / rs0, inv1 = 1.0f / rs1;

    size_t row0 = tok0 + wq + (lane >> 2);
    size_t row1 = row0 + 8;
#pragma unroll
    for (int j = 0; j < 8; j++) {
        int col = ho + j * 8 + 2 * (lane & 3);
        size_t o0 = row0 * DMODEL + col;
        size_t o1 = row1 * DMODEL + col;
        float2 x0 = *(const float2*)(x + o0);
        float2 x1v = *(const float2*)(x + o1);
        float2 r0 = { oacc[j][0] * inv0 + x0.x,  oacc[j][1] * inv0 + x0.y };
        float2 r1 = { oacc[j][2] * inv1 + x1v.x, oacc[j][3] * inv1 + x1v.y };
        *(float2*)(out + o0) = r0;
        *(float2*)(out + o1) = r1;
    }
}

// ---------------- HMMA plain-f16 GEMM: 256x128 tile, 3-stage, single sync/iter ----------------
#define GA_B   32768
#define GB_B   16384
#define GST_B  (GA_B + GB_B)

__device__ __forceinline__ void load_tile2(uint32_t sb,
    const __half* __restrict__ Ah, const __half* __restrict__ Bh,
    int m0, int n0, int K, int ic, int t)
{
#pragma unroll
    for (int i = 0; i < 8; i++) {
        int idx = t + 256 * i;
        int row = idx >> 3, ch = idx & 7;
        cp16(sw(sb, row, ch), Ah + (size_t)(m0 + row) * K + ic * 64 + ch * 8);
    }
#pragma unroll
    for (int i = 0; i < 4; i++) {
        int idx = t + 256 * i;
        int row = idx >> 3, ch = idx & 7;
        cp16(sw(sb + GA_B, row, ch), Bh + (size_t)(n0 + row) * K + ic * 64 + ch * 8);
    }
}

template<int MODE>
__global__ void __launch_bounds__(256, 1)
gemm_hmma_kernel(const __half* __restrict__ Ah, const __half* __restrict__ Bh,
                 const float* __restrict__ bias, const float* __restrict__ resid,
                 void* __restrict__ outp, int N, int K)
{
    extern __shared__ char dsm[];
    uint32_t smem_u32 = (uint32_t)__cvta_generic_to_shared(dsm);
    uint32_t base = (smem_u32 + 127) & ~127u;

    const int t = threadIdx.x;
    const int lane = t & 31, wid = t >> 5;
    const int m0 = blockIdx.y * 256, n0 = blockIdx.x * 128;
    const int warp_m = (wid >> 1) * 64, warp_n = (wid & 1) * 64;

    float acc[4][8][4] = {};
    const int NC = K >> 6;   // 12 (G1) or 48 (G2), always >= 3

    load_tile2(base,         Ah, Bh, m0, n0, K, 0, t);
    cp_commit();
    load_tile2(base + GST_B, Ah, Bh, m0, n0, K, 1, t);
    cp_commit();

    for (int ic = 0; ic < NC; ic++) {
        if (ic + 1 < NC) cp_wait1(); else cp_wait0();
        __syncthreads();   // buffer ic ready; also proves (ic+2)%3's old readers done

        if (ic + 2 < NC) {
            load_tile2(base + (uint32_t)((ic + 2) % 3) * GST_B, Ah, Bh, m0, n0, K, ic + 2, t);
            cp_commit();
        }

        uint32_t cb = base + (uint32_t)(ic % 3) * GST_B;
        uint32_t Ahb = cb, Bhb = cb + GA_B;
#pragma unroll
        for (int kp2 = 0; kp2 < 2; kp2++) {
            uint32_t ah[4][2][4];
#pragma unroll
            for (int mt = 0; mt < 4; mt++)
#pragma unroll
                for (int ks = 0; ks < 2; ks++) {
                    int row = warp_m + mt * 16 + (lane & 15);
                    int ch  = kp2 * 4 + ks * 2 + (lane >> 4);
                    ldsm4(ah[mt][ks], sw(Ahb, row, ch));
                }
#pragma unroll
            for (int np = 0; np < 4; np++) {
                uint32_t bh[2][4];
#pragma unroll
                for (int j = 0; j < 2; j++) {
                    int row = warp_n + (np * 2 + j) * 8 + (lane & 7);
                    int ch  = kp2 * 4 + ((lane >> 3) & 3);
                    ldsm4(bh[j], sw(Bhb, row, ch));
                }
#pragma unroll
                for (int ks = 0; ks < 2; ks++)
#pragma unroll
                    for (int mt = 0; mt < 4; mt++)
#pragma unroll
                        for (int j = 0; j < 2; j++)
                            mma_f16(acc[mt][np * 2 + j], ah[mt][ks], &bh[j][ks * 2]);
            }
        }
    }

    int rbase = m0 + warp_m + (lane >> 2);
    int cbase = n0 + warp_n + (lane & 3) * 2;
#pragma unroll
    for (int mt = 0; mt < 4; mt++)
#pragma unroll
        for (int nt = 0; nt < 8; nt++)
#pragma unroll
            for (int hh = 0; hh < 2; hh++) {
                int row = rbase + mt * 16 + hh * 8;
                int col = cbase + nt * 8;
                float v0 = acc[mt][nt][hh * 2 + 0] + bias[col];
                float v1 = acc[mt][nt][hh * 2 + 1] + bias[col + 1];
                size_t off = (size_t)row * N + col;
                if (MODE == 1) {
                    v0 = 0.5f * v0 * (1.0f + erff(v0 * 0.70710678118654752f));
                    v1 = 0.5f * v1 * (1.0f + erff(v1 * 0.70710678118654752f));
                    ((uint32_t*)outp)[off >> 1] = f16x2(v1, v0);
                } else {
                    const float2 rr = *(const float2*)(resid + off);
                    float2 ov = { v0 + rr.x, v1 + rr.y };
                    *(float2*)((float*)outp + off) = ov;
                }
            }
}

// ---------------- launch ----------------
extern "C" void kernel_launch(void* const* d_in, const int* in_sizes, int n_in,
                              void* d_out, int out_size)
{
    const float* x    = (const float*)d_in[0];
    const float* ln1g = (const float*)d_in[1];
    const float* ln1b = (const float*)d_in[2];
    const float* Wq   = (const float*)d_in[3];
    const float* bq   = (const float*)d_in[4];
    const float* Wk   = (const float*)d_in[5];
    const float* bk   = (const float*)d_in[6];
    const float* Wv   = (const float*)d_in[7];
    const float* bv   = (const float*)d_in[8];
    const float* ln2g = (const float*)d_in[9];
    const float* ln2b = (const float*)d_in[10];
    const float* W1   = (const float*)d_in[11];
    const float* b1   = (const float*)d_in[12];
    const float* W2   = (const float*)d_in[13];
    const float* b2   = (const float*)d_in[14];
    float* out = (float*)d_out;

    float* x1;
    __half *lnx, *lnh, *qf, *kf, *vt, *acth, *w1h, *w2h, *wqkv;
    cudaGetSymbolAddress((void**)&lnx,  g_lnx);
    cudaGetSymbolAddress((void**)&lnh,  g_lnh);
    cudaGetSymbolAddress((void**)&qf,   g_qf);
    cudaGetSymbolAddress((void**)&kf,   g_kf);
    cudaGetSymbolAddress((void**)&vt,   g_vt);
    cudaGetSymbolAddress((void**)&x1,   g_x1);
    cudaGetSymbolAddress((void**)&acth, g_acth);
    cudaGetSymbolAddress((void**)&w1h,  g_w1h);
    cudaGetSymbolAddress((void**)&w2h,  g_w2h);
    cudaGetSymbolAddress((void**)&wqkv, g_wqkv);

    const int ATTN_SMEM = 16384 + 3 * AT_BUF;   // 65536 (2 CTAs/SM)
    cudaFuncSetAttribute((const void*)attn_mma_kernel,
                         cudaFuncAttributeMaxDynamicSharedMemorySize, ATTN_SMEM);
    const int GEMM_SMEM = 3 * GST_B + 256;      // 147712 (1 CTA/SM)
    cudaFuncSetAttribute(gemm_hmma_kernel<1>,
                         cudaFuncAttributeMaxDynamicSharedMemorySize, GEMM_SMEM);
    cudaFuncSetAttribute(gemm_hmma_kernel<2>,
                         cudaFuncAttributeMaxDynamicSharedMemorySize, GEMM_SMEM);
    cudaFuncSetAttribute((const void*)qkv_mma_kernel,
                         cudaFuncAttributeMaxDynamicSharedMemorySize, QKV_SMEM);

    convert_w12_kernel<<<(DMLP * DMODEL + 255) / 256, 256>>>(W1, w1h, W2, w2h);
    convert_wqkv_kernel<<<(NHEAD * HDIM * HDIM + 255) / 256, 256>>>(Wq, Wk, Wv, wqkv);

    // 1) LN1 -> f16 (warp-per-token)
    ln_f16_kernel<<<TOKENS / 8, 256>>>(x, ln1g, ln1b, lnx);
    // 2) HMMA QKV (2 CTAs/SM)
    qkv_mma_kernel<<<dim3(TOKENS / 128, NHEAD), 256, QKV_SMEM>>>(
        lnx, wqkv, bq, bk, bv, qf, kf, vt);
    // 3) HMMA attention + residual -> x1
    attn_mma_kernel<<<dim3(SEQ / 128, NHEAD, BATCH), 256, ATTN_SMEM>>>(qf, kf, vt, x, x1);
    // 4) LN2 -> f16
    ln_f16_kernel<<<TOKENS / 8, 256>>>(x1, ln2g, ln2b, lnh);
    // 5) MLP up + GELU -> act f16 (3-stage)
    gemm_hmma_kernel<1><<<dim3(DMLP / 128, TOKENS / 256), 256, GEMM_SMEM>>>(
        lnh, w1h, b1, nullptr, (void*)acth, DMLP, DMODEL);
    // 6) MLP down + bias + residual -> out (3-stage)
    gemm_hmma_kernel<2><<<dim3(DMODEL / 128, TOKENS / 256), 256, GEMM_SMEM>>>(
        acth, w2h, b2, x1, (void*)out, DMODEL, DMLP);
}